// round 8
// baseline (speedup 1.0000x reference)
#include <cuda_runtime.h>
#include <stdint.h>

#define BATCH   2
#define SEQ     2048
#define DIM     1024
#define NHEAD   16
#define HDIM    64
#define MAXLEN  2048
#define BN      (BATCH*SEQ)

// ---------------- scratch (device globals; allocation is forbidden) ----------------
__device__ float g_Q[(size_t)BATCH * NHEAD * SEQ * HDIM];   // [(b*H+h)][n][hd]
__device__ float g_K[(size_t)BATCH * NHEAD * SEQ * HDIM];
__device__ float g_V[(size_t)BATCH * NHEAD * SEQ * HDIM];
__device__ float g_O[(size_t)BATCH * SEQ * DIM];            // [b][n][h*HD+hd]

// ---------------- helpers ----------------
__device__ __forceinline__ uint32_t f2t(float f) {
    uint32_t u;
    asm("cvt.rna.tf32.f32 %0, %1;" : "=r"(u) : "f"(f));
    return u;
}
__device__ __forceinline__ void split_tf32(float v, uint32_t& hi, uint32_t& lo) {
    hi = f2t(v);
    lo = f2t(v - __uint_as_float(hi));
}
__device__ __forceinline__ void mma8(float c[4],
                                     uint32_t a0, uint32_t a1, uint32_t a2, uint32_t a3,
                                     uint32_t b0, uint32_t b1) {
    asm volatile(
        "mma.sync.aligned.m16n8k8.row.col.f32.tf32.tf32.f32 "
        "{%0,%1,%2,%3},{%4,%5,%6,%7},{%8,%9},{%0,%1,%2,%3};"
        : "+f"(c[0]), "+f"(c[1]), "+f"(c[2]), "+f"(c[3])
        : "r"(a0), "r"(a1), "r"(a2), "r"(a3), "r"(b0), "r"(b1));
}

// ---------------- GEMM: C[m,n] = sum_k A[m,k] * W[n,k], 3xTF32 split ----------------
// MODE 0: A = g_O, write Cext[m*DIM+n] + bias[n]
// MODE 1: A = Aext(x), scatter to g_{Q,K,V}[((b*NH+h)*SEQ+n)*HD+hd] per sel
template<int MODE>
__global__ __launch_bounds__(256, 1)
void gemm_tn(const float* __restrict__ Aext, const float* __restrict__ W,
             const float* __restrict__ bias, float* __restrict__ Cext, int sel)
{
    __shared__ float As[16][132];
    __shared__ float Bs[16][132];

    const float* A = (MODE == 0) ? (const float*)g_O : Aext;

    const int m0 = blockIdx.y * 128;
    const int n0 = blockIdx.x * 128;
    const int tid = threadIdx.x;
    const int w = tid >> 5, lane = tid & 31, g = lane >> 2, t = lane & 3;
    const int wy = w >> 2, wx = w & 3;   // 2x4 warp grid; warp tile 64x32

    float acc[4][4][4];
#pragma unroll
    for (int i = 0; i < 4; i++)
#pragma unroll
        for (int j = 0; j < 4; j++)
#pragma unroll
            for (int e = 0; e < 4; e++) acc[i][j][e] = 0.f;

    for (int k0 = 0; k0 < DIM; k0 += 16) {
        __syncthreads();
#pragma unroll
        for (int i = 0; i < 2; i++) {
            int idx = tid + i * 256;            // 0..511 -> 128 rows x 4 float4
            int row = idx >> 2;
            int c4  = (idx & 3) << 2;
            float4 av = *(const float4*)(A + (size_t)(m0 + row) * DIM + k0 + c4);
            As[c4 + 0][row] = av.x; As[c4 + 1][row] = av.y;
            As[c4 + 2][row] = av.z; As[c4 + 3][row] = av.w;
            float4 bv = *(const float4*)(W + (size_t)(n0 + row) * DIM + k0 + c4);
            Bs[c4 + 0][row] = bv.x; Bs[c4 + 1][row] = bv.y;
            Bs[c4 + 2][row] = bv.z; Bs[c4 + 3][row] = bv.w;
        }
        __syncthreads();

#pragma unroll
        for (int ks = 0; ks < 2; ks++) {
            const int kk = ks * 8;
            uint32_t ah[4][4], al[4][4], bh[4][2], bl[4][2];
#pragma unroll
            for (int mt = 0; mt < 4; mt++) {
                int r = wy * 64 + mt * 16;
                split_tf32(As[kk + t][r + g],         ah[mt][0], al[mt][0]);
                split_tf32(As[kk + t][r + g + 8],     ah[mt][1], al[mt][1]);
                split_tf32(As[kk + t + 4][r + g],     ah[mt][2], al[mt][2]);
                split_tf32(As[kk + t + 4][r + g + 8], ah[mt][3], al[mt][3]);
            }
#pragma unroll
            for (int nt = 0; nt < 4; nt++) {
                int c = wx * 32 + nt * 8;
                split_tf32(Bs[kk + t][c + g],     bh[nt][0], bl[nt][0]);
                split_tf32(Bs[kk + t + 4][c + g], bh[nt][1], bl[nt][1]);
            }
#pragma unroll
            for (int mt = 0; mt < 4; mt++)
#pragma unroll
                for (int nt = 0; nt < 4; nt++) {
                    mma8(acc[mt][nt], ah[mt][0], ah[mt][1], ah[mt][2], ah[mt][3],
                         bh[nt][0], bh[nt][1]);
                    mma8(acc[mt][nt], ah[mt][0], ah[mt][1], ah[mt][2], ah[mt][3],
                         bl[nt][0], bl[nt][1]);
                    mma8(acc[mt][nt], al[mt][0], al[mt][1], al[mt][2], al[mt][3],
                         bh[nt][0], bh[nt][1]);
                }
        }
    }

    float* dstQKV = (MODE == 1) ? ((sel == 0) ? g_Q : ((sel == 1) ? g_K : g_V)) : nullptr;
#pragma unroll
    for (int mt = 0; mt < 4; mt++) {
        int rbase = wy * 64 + mt * 16 + g;
#pragma unroll
        for (int nt = 0; nt < 4; nt++) {
            int cbase = wx * 32 + nt * 8 + 2 * t;
#pragma unroll
            for (int e = 0; e < 4; e++) {
                int gm = m0 + rbase + ((e >= 2) ? 8 : 0);
                int gn = n0 + cbase + (e & 1);
                float v = acc[mt][nt][e];
                if (MODE == 0) {
                    Cext[(size_t)gm * DIM + gn] = v + bias[gn];
                } else {
                    int bb = gm / SEQ, nrow = gm % SEQ;
                    int hh = gn / HDIM, hd = gn % HDIM;
                    dstQKV[(((size_t)bb * NHEAD + hh) * SEQ + nrow) * HDIM + hd] = v;
                }
            }
        }
    }
}

// ---------------- fused causal attention with skewed relative positions ----------------
#define WQp 68
#define WEp 68
#define WGp 130
#define ATTN_SMEM_FLOATS (65*WQp + 64*WQp + 64*WQp + 128*WEp + 64*WGp)
#define ATTN_SMEM_BYTES  (ATTN_SMEM_FLOATS * 4)

__global__ __launch_bounds__(128, 1)
void attn_kernel(const float* __restrict__ rel)
{
    extern __shared__ float sm[];
    float* sQ  = sm;                    // [65][WQp]  q rows r0-1 .. r0+63
    float* sK  = sQ + 65 * WQp;         // [64][WQp]
    float* sV  = sK + 64 * WQp;         // [64][WQp]
    float* sE  = sV + 64 * WQp;         // [128][WEp]
    float* sGP = sE + 128 * WEp;        // [64][WGp]  G, then P (warp-private rows)

    const int qt = blockIdx.x;          // 0..31
    const int bh = blockIdx.y;          // 0..31
    const int r0 = qt * 64;
    const int b  = bh / NHEAD;
    const int h  = bh % NHEAD;
    const int hcol = h * HDIM;

    const float* Qg = g_Q + (size_t)bh * SEQ * HDIM;
    const float* Kg = g_K + (size_t)bh * SEQ * HDIM;
    const float* Vg = g_V + (size_t)bh * SEQ * HDIM;

    const int tid = threadIdx.x;
    const int w = tid >> 5, lane = tid & 31, g = lane >> 2, t = lane & 3;
    const int rA = w * 16 + g;          // tile-local rows rA and rA+8

    // stage Q rows r0-1 .. r0+63 (row -1 clamped; never consumed)
    for (int idx = tid; idx < 65 * 16; idx += 128) {
        int row = idx >> 4, c4 = (idx & 15) << 2;
        int gr = r0 - 1 + row; if (gr < 0) gr = 0;
        float4 v = *(const float4*)(Qg + (size_t)gr * HDIM + c4);
        float* d = sQ + row * WQp + c4;
        d[0] = v.x; d[1] = v.y; d[2] = v.z; d[3] = v.w;
    }
    __syncthreads();

    // persistent A-fragments: aQ = q rows (offset +1), aQp = q_{r-1} rows (offset 0)
    uint32_t aQ[8][4], aQp[8][4];
#pragma unroll
    for (int ks = 0; ks < 8; ks++) {
        int kk = ks * 8;
        aQ[ks][0]  = f2t(sQ[(1 + rA) * WQp + kk + t]);
        aQ[ks][1]  = f2t(sQ[(9 + rA) * WQp + kk + t]);
        aQ[ks][2]  = f2t(sQ[(1 + rA) * WQp + kk + t + 4]);
        aQ[ks][3]  = f2t(sQ[(9 + rA) * WQp + kk + t + 4]);
        aQp[ks][0] = f2t(sQ[(rA)     * WQp + kk + t]);
        aQp[ks][1] = f2t(sQ[(8 + rA) * WQp + kk + t]);
        aQp[ks][2] = f2t(sQ[(rA)     * WQp + kk + t + 4]);
        aQp[ks][3] = f2t(sQ[(8 + rA) * WQp + kk + t + 4]);
    }

    float Oacc[8][4];
#pragma unroll
    for (int i = 0; i < 8; i++)
#pragma unroll
        for (int e = 0; e < 4; e++) Oacc[i][e] = 0.f;
    float m0r = -1e30f, m1r = -1e30f;
    float l0r = 0.f,    l1r = 0.f;

    for (int j = 0; j <= qt; j++) {
        const int c0 = j * 64;
        __syncthreads();   // previous iteration's sK/sV/sE readers are done

        // stage K, V tiles
        for (int idx = tid; idx < 64 * 16; idx += 128) {
            int row = idx >> 4, c4 = (idx & 15) << 2;
            float4 kv = *(const float4*)(Kg + (size_t)(c0 + row) * HDIM + c4);
            float* dk = sK + row * WQp + c4;
            dk[0] = kv.x; dk[1] = kv.y; dk[2] = kv.z; dk[3] = kv.w;
            float4 vv = *(const float4*)(Vg + (size_t)(c0 + row) * HDIM + c4);
            float* dv = sV + row * WQp + c4;
            dv[0] = vv.x; dv[1] = vv.y; dv[2] = vv.z; dv[3] = vv.w;
        }
        // stage E window: sE row `row` holds logical e-index elog0+row; rows >= SEQ zero
        const int elog0 = SEQ - r0 + c0 - 63;   // >= 1 always
        for (int idx = tid; idx < 128 * 16; idx += 128) {
            int row = idx >> 4, c4 = (idx & 15) << 2;
            int el = elog0 + row;
            float4 ev = make_float4(0.f, 0.f, 0.f, 0.f);
            if (el < SEQ)
                ev = *(const float4*)(rel + (size_t)(el + (MAXLEN - SEQ)) * DIM + hcol + c4);
            float* de = sE + row * WEp + c4;
            de[0] = ev.x; de[1] = ev.y; de[2] = ev.z; de[3] = ev.w;
        }
        __syncthreads();

        // ---- G = Qprev @ Ewin^T (64 x 128), warp-private rows in sGP ----
#pragma unroll
        for (int nt = 0; nt < 16; nt++) {
            float ga[4] = {0.f, 0.f, 0.f, 0.f};
            const int er = nt * 8 + g;
#pragma unroll
            for (int ks = 0; ks < 8; ks++) {
                int kk = ks * 8;
                uint32_t b0 = f2t(sE[er * WEp + kk + t]);
                uint32_t b1 = f2t(sE[er * WEp + kk + t + 4]);
                mma8(ga, aQp[ks][0], aQp[ks][1], aQp[ks][2], aQp[ks][3], b0, b1);
            }
            int cc = nt * 8 + 2 * t;
            sGP[(rA)     * WGp + cc]     = ga[0];
            sGP[(rA)     * WGp + cc + 1] = ga[1];
            sGP[(rA + 8) * WGp + cc]     = ga[2];
            sGP[(rA + 8) * WGp + cc + 1] = ga[3];
        }
        __syncwarp();

        // ---- S = Q @ K^T + srel (diagonal gather of G), mask, scale ----
        float Sreg[8][4];
        float tmax0 = -1e30f, tmax1 = -1e30f;
#pragma unroll
        for (int nt = 0; nt < 8; nt++) {
            float* s = Sreg[nt];
            s[0] = s[1] = s[2] = s[3] = 0.f;
            const int kr = nt * 8 + g;
#pragma unroll
            for (int ks = 0; ks < 8; ks++) {
                int kk = ks * 8;
                uint32_t b0 = f2t(sK[kr * WQp + kk + t]);
                uint32_t b1 = f2t(sK[kr * WQp + kk + t + 4]);
                mma8(s, aQ[ks][0], aQ[ks][1], aQ[ks][2], aQ[ks][3], b0, b1);
            }
            const int cc0 = nt * 8 + 2 * t;
            float v;
            v = (s[0] + sGP[rA * WGp + 63 + cc0 - rA]) * 0.125f;
            if (c0 + cc0 > r0 + rA) v = -1e30f;
            s[0] = v; tmax0 = fmaxf(tmax0, v);

            v = (s[1] + sGP[rA * WGp + 64 + cc0 - rA]) * 0.125f;
            if (c0 + cc0 + 1 > r0 + rA) v = -1e30f;
            s[1] = v; tmax0 = fmaxf(tmax0, v);

            v = (s[2] + sGP[(rA + 8) * WGp + 55 + cc0 - rA]) * 0.125f;
            if (c0 + cc0 > r0 + rA + 8) v = -1e30f;
            s[2] = v; tmax1 = fmaxf(tmax1, v);

            v = (s[3] + sGP[(rA + 8) * WGp + 56 + cc0 - rA]) * 0.125f;
            if (c0 + cc0 + 1 > r0 + rA + 8) v = -1e30f;
            s[3] = v; tmax1 = fmaxf(tmax1, v);
        }

        // quad reductions (lanes 4g..4g+3 share the same two rows)
        tmax0 = fmaxf(tmax0, __shfl_xor_sync(0xffffffffu, tmax0, 1));
        tmax0 = fmaxf(tmax0, __shfl_xor_sync(0xffffffffu, tmax0, 2));
        tmax1 = fmaxf(tmax1, __shfl_xor_sync(0xffffffffu, tmax1, 1));
        tmax1 = fmaxf(tmax1, __shfl_xor_sync(0xffffffffu, tmax1, 2));

        float mn0 = fmaxf(m0r, tmax0), mn1 = fmaxf(m1r, tmax1);
        float f0 = __expf(m0r - mn0),  f1 = __expf(m1r - mn1);
        float rs0 = 0.f, rs1 = 0.f;
#pragma unroll
        for (int nt = 0; nt < 8; nt++) {
            float* s = Sreg[nt];
            s[0] = __expf(s[0] - mn0); s[1] = __expf(s[1] - mn0);
            s[2] = __expf(s[2] - mn1); s[3] = __expf(s[3] - mn1);
            rs0 += s[0] + s[1];
            rs1 += s[2] + s[3];
        }
        rs0 += __shfl_xor_sync(0xffffffffu, rs0, 1);
        rs0 += __shfl_xor_sync(0xffffffffu, rs0, 2);
        rs1 += __shfl_xor_sync(0xffffffffu, rs1, 1);
        rs1 += __shfl_xor_sync(0xffffffffu, rs1, 2);

        m0r = mn0; m1r = mn1;
        l0r = l0r * f0 + rs0;
        l1r = l1r * f1 + rs1;
#pragma unroll
        for (int dn = 0; dn < 8; dn++) {
            Oacc[dn][0] *= f0; Oacc[dn][1] *= f0;
            Oacc[dn][2] *= f1; Oacc[dn][3] *= f1;
        }

        __syncwarp();   // all gather reads of G done before overwriting with P
#pragma unroll
        for (int nt = 0; nt < 8; nt++) {
            int cc0 = nt * 8 + 2 * t;
            sGP[(rA)     * WGp + cc0]     = Sreg[nt][0];
            sGP[(rA)     * WGp + cc0 + 1] = Sreg[nt][1];
            sGP[(rA + 8) * WGp + cc0]     = Sreg[nt][2];
            sGP[(rA + 8) * WGp + cc0 + 1] = Sreg[nt][3];
        }
        __syncwarp();

        // ---- O += P @ V ----
        uint32_t aP[8][4];
#pragma unroll
        for (int ks = 0; ks < 8; ks++) {
            int kk = ks * 8;
            aP[ks][0] = f2t(sGP[(rA)     * WGp + kk + t]);
            aP[ks][1] = f2t(sGP[(rA + 8) * WGp + kk + t]);
            aP[ks][2] = f2t(sGP[(rA)     * WGp + kk + t + 4]);
            aP[ks][3] = f2t(sGP[(rA + 8) * WGp + kk + t + 4]);
        }
#pragma unroll
        for (int dn = 0; dn < 8; dn++) {
            const int nb = dn * 8 + g;
#pragma unroll
            for (int ks = 0; ks < 8; ks++) {
                int kk = ks * 8;
                uint32_t b0 = f2t(sV[(kk + t)     * WQp + nb]);
                uint32_t b1 = f2t(sV[(kk + t + 4) * WQp + nb]);
                mma8(Oacc[dn], aP[ks][0], aP[ks][1], aP[ks][2], aP[ks][3], b0, b1);
            }
        }
    }

    // ---- normalize and write O in [b][n][h*HD+hd] layout ----
    float inv0 = 1.f / l0r, inv1 = 1.f / l1r;
    float* Og = g_O + (size_t)b * SEQ * DIM + (size_t)r0 * DIM + hcol;
#pragma unroll
    for (int dn = 0; dn < 8; dn++) {
        int d0 = dn * 8 + 2 * t;
        Og[(size_t)(rA)     * DIM + d0]     = Oacc[dn][0] * inv0;
        Og[(size_t)(rA)     * DIM + d0 + 1] = Oacc[dn][1] * inv0;
        Og[(size_t)(rA + 8) * DIM + d0]     = Oacc[dn][2] * inv1;
        Og[(size_t)(rA + 8) * DIM + d0 + 1] = Oacc[dn][3] * inv1;
    }
}

// ---------------- launch ----------------
extern "C" void kernel_launch(void* const* d_in, const int* in_sizes, int n_in,
                              void* d_out, int out_size)
{
    const float* x   = (const float*)d_in[0];
    const float* Wq  = (const float*)d_in[1];
    const float* Wk  = (const float*)d_in[2];
    const float* Wv  = (const float*)d_in[3];
    const float* Wp  = (const float*)d_in[4];
    const float* bp  = (const float*)d_in[5];
    const float* rel = (const float*)d_in[6];
    float* out = (float*)d_out;

    cudaFuncSetAttribute(attn_kernel,
                         cudaFuncAttributeMaxDynamicSharedMemorySize,
                         ATTN_SMEM_BYTES);

    dim3 gg(DIM / 128, BN / 128);
    gemm_tn<1><<<gg, 256>>>(x, Wq, nullptr, nullptr, 0);
    gemm_tn<1><<<gg, 256>>>(x, Wk, nullptr, nullptr, 1);
    gemm_tn<1><<<gg, 256>>>(x, Wv, nullptr, nullptr, 2);
    attn_kernel<<<dim3(SEQ / 64, BATCH * NHEAD), 128, ATTN_SMEM_BYTES>>>(rel);
    gemm_tn<0><<<gg, 256>>>(nullptr, Wp, bp, out, 0);
}

// round 9
// speedup vs baseline: 2.8445x; 2.8445x over previous
#include <cuda_runtime.h>
#include <stdint.h>

#define BATCH   2
#define SEQ     2048
#define DIM     1024
#define NHEAD   16
#define HDIM    64
#define MAXLEN  2048
#define BN      (BATCH*SEQ)

// ---------------- scratch (device globals; allocation is forbidden) ----------------
__device__ float g_Q[(size_t)BATCH * NHEAD * SEQ * HDIM];   // [(b*H+h)][n][hd]
__device__ float g_K[(size_t)BATCH * NHEAD * SEQ * HDIM];
__device__ float g_V[(size_t)BATCH * NHEAD * SEQ * HDIM];
__device__ float g_O[(size_t)BATCH * SEQ * DIM];            // [b][n][h*HD+hd]

// ---------------- helpers ----------------
__device__ __forceinline__ uint32_t f2t(float f) {
    uint32_t u;
    asm("cvt.rna.tf32.f32 %0, %1;" : "=r"(u) : "f"(f));
    return u;
}
__device__ __forceinline__ float f2tf(float f) {
    return __uint_as_float(f2t(f));
}
__device__ __forceinline__ void mma8(float c[4],
                                     uint32_t a0, uint32_t a1, uint32_t a2, uint32_t a3,
                                     uint32_t b0, uint32_t b1) {
    asm volatile(
        "mma.sync.aligned.m16n8k8.row.col.f32.tf32.tf32.f32 "
        "{%0,%1,%2,%3},{%4,%5,%6,%7},{%8,%9},{%0,%1,%2,%3};"
        : "+f"(c[0]), "+f"(c[1]), "+f"(c[2]), "+f"(c[3])
        : "r"(a0), "r"(a1), "r"(a2), "r"(a3), "r"(b0), "r"(b1));
}

// ---------------- GEMM: C[m,n] = sum_k A[m,k] * W[n,k], 1x tf32 ----------------
// MODE 0: A = g_O, C = Cext[m*DIM+n] + bias[n]
// MODE 1: A = Aext(x), W = {W0,W1,W2}[blockIdx.z], scatter to g_{Q,K,V}
template<int MODE>
__global__ __launch_bounds__(256, 2)
void gemm_tn(const float* __restrict__ Aext,
             const float* __restrict__ W0, const float* __restrict__ W1,
             const float* __restrict__ W2,
             const float* __restrict__ bias, float* __restrict__ Cext)
{
    __shared__ float As[16][132];   // tf32 bits, [k][m]
    __shared__ float Bs[16][132];   // tf32 bits, [k][n]

    const int sel = (MODE == 1) ? blockIdx.z : 0;
    const float* W = (MODE == 0) ? W0 : ((sel == 0) ? W0 : (sel == 1) ? W1 : W2);
    const float* A = (MODE == 0) ? (const float*)g_O : Aext;

    const int m0 = blockIdx.y * 128;
    const int n0 = blockIdx.x * 128;
    const int tid = threadIdx.x;
    const int w = tid >> 5, lane = tid & 31, g = lane >> 2, t = lane & 3;
    const int wy = w >> 2, wx = w & 3;   // 2x4 warp grid; warp tile 64x32

    float acc[4][4][4];
#pragma unroll
    for (int i = 0; i < 4; i++)
#pragma unroll
        for (int j = 0; j < 4; j++)
#pragma unroll
            for (int e = 0; e < 4; e++) acc[i][j][e] = 0.f;

    for (int k0 = 0; k0 < DIM; k0 += 16) {
        __syncthreads();
#pragma unroll
        for (int i = 0; i < 2; i++) {
            int idx = tid + i * 256;            // 0..511 -> 128 rows x 4 float4
            int row = idx >> 2;
            int c4  = (idx & 3) << 2;
            float4 av = *(const float4*)(A + (size_t)(m0 + row) * DIM + k0 + c4);
            As[c4 + 0][row] = f2tf(av.x); As[c4 + 1][row] = f2tf(av.y);
            As[c4 + 2][row] = f2tf(av.z); As[c4 + 3][row] = f2tf(av.w);
            float4 bv = *(const float4*)(W + (size_t)(n0 + row) * DIM + k0 + c4);
            Bs[c4 + 0][row] = f2tf(bv.x); Bs[c4 + 1][row] = f2tf(bv.y);
            Bs[c4 + 2][row] = f2tf(bv.z); Bs[c4 + 3][row] = f2tf(bv.w);
        }
        __syncthreads();

#pragma unroll
        for (int ks = 0; ks < 2; ks++) {
            const int kk = ks * 8;
            uint32_t af[4][4], bf[4][2];
#pragma unroll
            for (int mt = 0; mt < 4; mt++) {
                int r = wy * 64 + mt * 16;
                af[mt][0] = __float_as_uint(As[kk + t][r + g]);
                af[mt][1] = __float_as_uint(As[kk + t][r + g + 8]);
                af[mt][2] = __float_as_uint(As[kk + t + 4][r + g]);
                af[mt][3] = __float_as_uint(As[kk + t + 4][r + g + 8]);
            }
#pragma unroll
            for (int nt = 0; nt < 4; nt++) {
                int c = wx * 32 + nt * 8;
                bf[nt][0] = __float_as_uint(Bs[kk + t][c + g]);
                bf[nt][1] = __float_as_uint(Bs[kk + t + 4][c + g]);
            }
#pragma unroll
            for (int mt = 0; mt < 4; mt++)
#pragma unroll
                for (int nt = 0; nt < 4; nt++)
                    mma8(acc[mt][nt], af[mt][0], af[mt][1], af[mt][2], af[mt][3],
                         bf[nt][0], bf[nt][1]);
        }
    }

    float* dstQKV = (MODE == 1) ? ((sel == 0) ? g_Q : ((sel == 1) ? g_K : g_V)) : nullptr;
#pragma unroll
    for (int mt = 0; mt < 4; mt++) {
        int rbase = wy * 64 + mt * 16 + g;
#pragma unroll
        for (int nt = 0; nt < 4; nt++) {
            int cbase = wx * 32 + nt * 8 + 2 * t;
#pragma unroll
            for (int e = 0; e < 4; e++) {
                int gm = m0 + rbase + ((e >= 2) ? 8 : 0);
                int gn = n0 + cbase + (e & 1);
                float v = acc[mt][nt][e];
                if (MODE == 0) {
                    Cext[(size_t)gm * DIM + gn] = v + bias[gn];
                } else {
                    int bb = gm / SEQ, nrow = gm % SEQ;
                    int hh = gn / HDIM, hd = gn % HDIM;
                    dstQKV[(((size_t)bb * NHEAD + hh) * SEQ + nrow) * HDIM + hd] = v;
                }
            }
        }
    }
}

// ---------------- fused causal attention with skewed relative positions ----------------
// srel[r,c] = q_{r-1} . e_{N-(r-c)} for c<r, 0 at c==r (via zero-filled E rows >= N).
// G banded: Gb[r][i] = G[r][63-r+i], i in [0,64). Consumer gather index is then just cc.
#define WQp 68
#define WEp 68
#define GBW 65
#define ATTN_SMEM_FLOATS (65*WQp + 64*WQp + 64*WQp + 128*WEp + 64*GBW)
#define ATTN_SMEM_BYTES  (ATTN_SMEM_FLOATS * 4)

__global__ __launch_bounds__(128, 2)
void attn_kernel(const float* __restrict__ rel)
{
    extern __shared__ float sm[];
    float* sQ  = sm;                    // [65][WQp]  tf32 bits, q rows r0-1..r0+63
    float* sK  = sQ + 65 * WQp;         // [64][WQp]  tf32 bits
    float* sV  = sK + 64 * WQp;         // [64][WQp]  tf32 bits
    float* sE  = sV + 64 * WQp;         // [128][WEp] tf32 bits
    float* sGb = sE + 128 * WEp;        // [64][GBW]  G band / P (warp-private rows)

    const int qt = blockIdx.x;          // 0..31
    const int bh = blockIdx.y;          // 0..31
    const int r0 = qt * 64;
    const int b  = bh / NHEAD;
    const int h  = bh % NHEAD;
    const int hcol = h * HDIM;

    const float* Qg = g_Q + (size_t)bh * SEQ * HDIM;
    const float* Kg = g_K + (size_t)bh * SEQ * HDIM;
    const float* Vg = g_V + (size_t)bh * SEQ * HDIM;

    const int tid = threadIdx.x;
    const int w = tid >> 5, lane = tid & 31, g = lane >> 2, t = lane & 3;
    const int rA = w * 16 + g;          // tile-local rows rA and rA+8

    // stage Q rows r0-1 .. r0+63 (row -1 clamped; never consumed), pre-cvt tf32
    for (int idx = tid; idx < 65 * 16; idx += 128) {
        int row = idx >> 4, c4 = (idx & 15) << 2;
        int gr = r0 - 1 + row; if (gr < 0) gr = 0;
        float4 v = *(const float4*)(Qg + (size_t)gr * HDIM + c4);
        float* d = sQ + row * WQp + c4;
        d[0] = f2tf(v.x); d[1] = f2tf(v.y); d[2] = f2tf(v.z); d[3] = f2tf(v.w);
    }
    __syncthreads();

    // persistent A-fragments: aQ = q rows (offset +1), aQp = q_{r-1} rows (offset 0)
    uint32_t aQ[8][4], aQp[8][4];
#pragma unroll
    for (int ks = 0; ks < 8; ks++) {
        int kk = ks * 8;
        aQ[ks][0]  = __float_as_uint(sQ[(1 + rA) * WQp + kk + t]);
        aQ[ks][1]  = __float_as_uint(sQ[(9 + rA) * WQp + kk + t]);
        aQ[ks][2]  = __float_as_uint(sQ[(1 + rA) * WQp + kk + t + 4]);
        aQ[ks][3]  = __float_as_uint(sQ[(9 + rA) * WQp + kk + t + 4]);
        aQp[ks][0] = __float_as_uint(sQ[(rA)     * WQp + kk + t]);
        aQp[ks][1] = __float_as_uint(sQ[(8 + rA) * WQp + kk + t]);
        aQp[ks][2] = __float_as_uint(sQ[(rA)     * WQp + kk + t + 4]);
        aQp[ks][3] = __float_as_uint(sQ[(8 + rA) * WQp + kk + t + 4]);
    }

    float Oacc[8][4];
#pragma unroll
    for (int i = 0; i < 8; i++)
#pragma unroll
        for (int e = 0; e < 4; e++) Oacc[i][e] = 0.f;
    float m0r = -1e30f, m1r = -1e30f;
    float l0r = 0.f,    l1r = 0.f;

    for (int j = 0; j <= qt; j++) {
        const int c0 = j * 64;
        __syncthreads();   // previous iteration's sK/sV/sE readers are done

        // stage K, V tiles (pre-cvt tf32)
        for (int idx = tid; idx < 64 * 16; idx += 128) {
            int row = idx >> 4, c4 = (idx & 15) << 2;
            float4 kv = *(const float4*)(Kg + (size_t)(c0 + row) * HDIM + c4);
            float* dk = sK + row * WQp + c4;
            dk[0] = f2tf(kv.x); dk[1] = f2tf(kv.y); dk[2] = f2tf(kv.z); dk[3] = f2tf(kv.w);
            float4 vv = *(const float4*)(Vg + (size_t)(c0 + row) * HDIM + c4);
            float* dv = sV + row * WQp + c4;
            dv[0] = f2tf(vv.x); dv[1] = f2tf(vv.y); dv[2] = f2tf(vv.z); dv[3] = f2tf(vv.w);
        }
        // stage E window: sE row holds logical e-index elog0+row; rows >= SEQ zero-filled
        const int elog0 = SEQ - r0 + c0 - 63;   // >= 1 always
        for (int idx = tid; idx < 128 * 16; idx += 128) {
            int row = idx >> 4, c4 = (idx & 15) << 2;
            int el = elog0 + row;
            float4 ev = make_float4(0.f, 0.f, 0.f, 0.f);
            if (el < SEQ)
                ev = *(const float4*)(rel + (size_t)(el + (MAXLEN - SEQ)) * DIM + hcol + c4);
            float* de = sE + row * WEp + c4;
            de[0] = f2tf(ev.x); de[1] = f2tf(ev.y); de[2] = f2tf(ev.z); de[3] = f2tf(ev.w);
        }
        __syncthreads();

        // ---- G band = Qprev @ Ewin^T, only the n-tiles this warp's rows consume ----
        // rows 16w..16w+15 need G cols [48-16w, 126-16w] -> nt in [6-2w, 15-2w]
        const int nt0 = 6 - 2 * w;
#pragma unroll
        for (int ntl = 0; ntl < 10; ntl++) {
            const int nt = nt0 + ntl;
            float ga[4] = {0.f, 0.f, 0.f, 0.f};
            const int er = nt * 8 + g;
#pragma unroll
            for (int ks = 0; ks < 8; ks++) {
                int kk = ks * 8;
                uint32_t b0 = __float_as_uint(sE[er * WEp + kk + t]);
                uint32_t b1 = __float_as_uint(sE[er * WEp + kk + t + 4]);
                mma8(ga, aQp[ks][0], aQp[ks][1], aQp[ks][2], aQp[ks][3], b0, b1);
            }
            const int cc = nt * 8 + 2 * t;
            const int i0 = cc + rA - 63;        // band index for row rA
            const int i2 = i0 + 8;              // band index for row rA+8
            if (i0 >= 0     && i0 < 64)     sGb[(rA)     * GBW + i0]     = ga[0];
            if (i0 + 1 >= 0 && i0 + 1 < 64) sGb[(rA)     * GBW + i0 + 1] = ga[1];
            if (i2 >= 0     && i2 < 64)     sGb[(rA + 8) * GBW + i2]     = ga[2];
            if (i2 + 1 >= 0 && i2 + 1 < 64) sGb[(rA + 8) * GBW + i2 + 1] = ga[3];
        }
        __syncwarp();

        // ---- S = Q @ K^T + srel (band gather), mask, scale ----
        float Sreg[8][4];
        float tmax0 = -1e30f, tmax1 = -1e30f;
#pragma unroll
        for (int nt = 0; nt < 8; nt++) {
            float* s = Sreg[nt];
            s[0] = s[1] = s[2] = s[3] = 0.f;
            const int kr = nt * 8 + g;
#pragma unroll
            for (int ks = 0; ks < 8; ks++) {
                int kk = ks * 8;
                uint32_t b0 = __float_as_uint(sK[kr * WQp + kk + t]);
                uint32_t b1 = __float_as_uint(sK[kr * WQp + kk + t + 4]);
                mma8(s, aQ[ks][0], aQ[ks][1], aQ[ks][2], aQ[ks][3], b0, b1);
            }
            const int cc0 = nt * 8 + 2 * t;
            float v;
            v = (s[0] + sGb[rA * GBW + cc0]) * 0.125f;
            if (c0 + cc0 > r0 + rA) v = -1e30f;
            s[0] = v; tmax0 = fmaxf(tmax0, v);

            v = (s[1] + sGb[rA * GBW + cc0 + 1]) * 0.125f;
            if (c0 + cc0 + 1 > r0 + rA) v = -1e30f;
            s[1] = v; tmax0 = fmaxf(tmax0, v);

            v = (s[2] + sGb[(rA + 8) * GBW + cc0]) * 0.125f;
            if (c0 + cc0 > r0 + rA + 8) v = -1e30f;
            s[2] = v; tmax1 = fmaxf(tmax1, v);

            v = (s[3] + sGb[(rA + 8) * GBW + cc0 + 1]) * 0.125f;
            if (c0 + cc0 + 1 > r0 + rA + 8) v = -1e30f;
            s[3] = v; tmax1 = fmaxf(tmax1, v);
        }

        // quad reductions (lanes sharing rows)
        tmax0 = fmaxf(tmax0, __shfl_xor_sync(0xffffffffu, tmax0, 1));
        tmax0 = fmaxf(tmax0, __shfl_xor_sync(0xffffffffu, tmax0, 2));
        tmax1 = fmaxf(tmax1, __shfl_xor_sync(0xffffffffu, tmax1, 1));
        tmax1 = fmaxf(tmax1, __shfl_xor_sync(0xffffffffu, tmax1, 2));

        float mn0 = fmaxf(m0r, tmax0), mn1 = fmaxf(m1r, tmax1);
        float f0 = __expf(m0r - mn0),  f1 = __expf(m1r - mn1);
        float rs0 = 0.f, rs1 = 0.f;
#pragma unroll
        for (int nt = 0; nt < 8; nt++) {
            float* s = Sreg[nt];
            s[0] = __expf(s[0] - mn0); s[1] = __expf(s[1] - mn0);
            s[2] = __expf(s[2] - mn1); s[3] = __expf(s[3] - mn1);
            rs0 += s[0] + s[1];
            rs1 += s[2] + s[3];
        }
        rs0 += __shfl_xor_sync(0xffffffffu, rs0, 1);
        rs0 += __shfl_xor_sync(0xffffffffu, rs0, 2);
        rs1 += __shfl_xor_sync(0xffffffffu, rs1, 1);
        rs1 += __shfl_xor_sync(0xffffffffu, rs1, 2);

        m0r = mn0; m1r = mn1;
        l0r = l0r * f0 + rs0;
        l1r = l1r * f1 + rs1;
#pragma unroll
        for (int dn = 0; dn < 8; dn++) {
            Oacc[dn][0] *= f0; Oacc[dn][1] *= f0;
            Oacc[dn][2] *= f1; Oacc[dn][3] *= f1;
        }

        __syncwarp();   // all band-gather reads done before overwriting with P
#pragma unroll
        for (int nt = 0; nt < 8; nt++) {
            int cc0 = nt * 8 + 2 * t;
            sGb[(rA)     * GBW + cc0]     = f2tf(Sreg[nt][0]);
            sGb[(rA)     * GBW + cc0 + 1] = f2tf(Sreg[nt][1]);
            sGb[(rA + 8) * GBW + cc0]     = f2tf(Sreg[nt][2]);
            sGb[(rA + 8) * GBW + cc0 + 1] = f2tf(Sreg[nt][3]);
        }
        __syncwarp();

        // ---- O += P @ V ----
        uint32_t aP[8][4];
#pragma unroll
        for (int ks = 0; ks < 8; ks++) {
            int kk = ks * 8;
            aP[ks][0] = __float_as_uint(sGb[(rA)     * GBW + kk + t]);
            aP[ks][1] = __float_as_uint(sGb[(rA + 8) * GBW + kk + t]);
            aP[ks][2] = __float_as_uint(sGb[(rA)     * GBW + kk + t + 4]);
            aP[ks][3] = __float_as_uint(sGb[(rA + 8) * GBW + kk + t + 4]);
        }
#pragma unroll
        for (int dn = 0; dn < 8; dn++) {
            const int nb = dn * 8 + g;
#pragma unroll
            for (int ks = 0; ks < 8; ks++) {
                int kk = ks * 8;
                uint32_t b0 = __float_as_uint(sV[(kk + t)     * WQp + nb]);
                uint32_t b1 = __float_as_uint(sV[(kk + t + 4) * WQp + nb]);
                mma8(Oacc[dn], aP[ks][0], aP[ks][1], aP[ks][2], aP[ks][3], b0, b1);
            }
        }
    }

    // ---- normalize and write O in [b][n][h*HD+hd] layout ----
    float inv0 = 1.f / l0r, inv1 = 1.f / l1r;
    float* Og = g_O + (size_t)b * SEQ * DIM + (size_t)r0 * DIM + hcol;
#pragma unroll
    for (int dn = 0; dn < 8; dn++) {
        int d0 = dn * 8 + 2 * t;
        Og[(size_t)(rA)     * DIM + d0]     = Oacc[dn][0] * inv0;
        Og[(size_t)(rA)     * DIM + d0 + 1] = Oacc[dn][1] * inv0;
        Og[(size_t)(rA + 8) * DIM + d0]     = Oacc[dn][2] * inv1;
        Og[(size_t)(rA + 8) * DIM + d0 + 1] = Oacc[dn][3] * inv1;
    }
}

// ---------------- launch ----------------
extern "C" void kernel_launch(void* const* d_in, const int* in_sizes, int n_in,
                              void* d_out, int out_size)
{
    const float* x   = (const float*)d_in[0];
    const float* Wq  = (const float*)d_in[1];
    const float* Wk  = (const float*)d_in[2];
    const float* Wv  = (const float*)d_in[3];
    const float* Wp  = (const float*)d_in[4];
    const float* bp  = (const float*)d_in[5];
    const float* rel = (const float*)d_in[6];
    float* out = (float*)d_out;

    cudaFuncSetAttribute(attn_kernel,
                         cudaFuncAttributeMaxDynamicSharedMemorySize,
                         ATTN_SMEM_BYTES);

    gemm_tn<1><<<dim3(DIM / 128, BN / 128, 3), 256>>>(x, Wq, Wk, Wv, nullptr, nullptr);
    attn_kernel<<<dim3(SEQ / 64, BATCH * NHEAD), 128, ATTN_SMEM_BYTES>>>(rel);
    gemm_tn<0><<<dim3(DIM / 128, BN / 128), 256>>>(nullptr, Wp, nullptr, nullptr, bp, out);
}

// round 10
// speedup vs baseline: 3.1902x; 1.1215x over previous
#include <cuda_runtime.h>
#include <stdint.h>

#define BATCH   2
#define SEQ     2048
#define DIM     1024
#define NHEAD   16
#define HDIM    64
#define MAXLEN  2048
#define BN      (BATCH*SEQ)

// ---------------- scratch (device globals; allocation is forbidden) ----------------
__device__ float g_Q[(size_t)BATCH * NHEAD * SEQ * HDIM];   // [(b*H+h)][n][hd]
__device__ float g_K[(size_t)BATCH * NHEAD * SEQ * HDIM];
__device__ float g_V[(size_t)BATCH * NHEAD * SEQ * HDIM];
__device__ float g_O[(size_t)BATCH * SEQ * DIM];            // [b][n][h*HD+hd]

// ---------------- helpers ----------------
__device__ __forceinline__ uint32_t f2t(float f) {
    uint32_t u;
    asm("cvt.rna.tf32.f32 %0, %1;" : "=r"(u) : "f"(f));
    return u;
}
__device__ __forceinline__ float f2tf(float f) {
    return __uint_as_float(f2t(f));
}
__device__ __forceinline__ float4 cvt4(float4 v) {
    return make_float4(f2tf(v.x), f2tf(v.y), f2tf(v.z), f2tf(v.w));
}
__device__ __forceinline__ void mma8(float c[4],
                                     uint32_t a0, uint32_t a1, uint32_t a2, uint32_t a3,
                                     uint32_t b0, uint32_t b1) {
    asm volatile(
        "mma.sync.aligned.m16n8k8.row.col.f32.tf32.tf32.f32 "
        "{%0,%1,%2,%3},{%4,%5,%6,%7},{%8,%9},{%0,%1,%2,%3};"
        : "+f"(c[0]), "+f"(c[1]), "+f"(c[2]), "+f"(c[3])
        : "r"(a0), "r"(a1), "r"(a2), "r"(a3), "r"(b0), "r"(b1));
}

// ---------------- GEMM: C[m,n] = sum_k A[m,k] * W[n,k], 1x tf32 ----------------
// [m][k] smem layout (pad 20): conflict-free fragment LDS + STS.128 staging,
// double-buffered over k-blocks of 16.
// MODE 0: A = g_O, C = Cext[m*DIM+n] + bias[n]
// MODE 1: A = Aext(x), W = {W0,W1,W2}[blockIdx.z], scatter to g_{Q,K,V}
#define KP 20
template<int MODE>
__global__ __launch_bounds__(256, 2)
void gemm_tn(const float* __restrict__ Aext,
             const float* __restrict__ W0, const float* __restrict__ W1,
             const float* __restrict__ W2,
             const float* __restrict__ bias, float* __restrict__ Cext)
{
    __align__(16) __shared__ float As[2][128][KP];   // tf32 bits, [m][k]
    __align__(16) __shared__ float Bs[2][128][KP];   // tf32 bits, [n][k]

    const int sel = (MODE == 1) ? blockIdx.z : 0;
    const float* W = (MODE == 0) ? W0 : ((sel == 0) ? W0 : (sel == 1) ? W1 : W2);
    const float* A = (MODE == 0) ? (const float*)g_O : Aext;

    const int m0 = blockIdx.y * 128;
    const int n0 = blockIdx.x * 128;
    const int tid = threadIdx.x;
    const int w = tid >> 5, lane = tid & 31, g = lane >> 2, t = lane & 3;
    const int wy = w >> 2, wx = w & 3;   // 2x4 warp grid; warp tile 64x32

    const int srow = tid >> 2;           // 0..63
    const int sc4  = (tid & 3) << 2;     // 0,4,8,12

    float acc[4][4][4];
#pragma unroll
    for (int i = 0; i < 4; i++)
#pragma unroll
        for (int j = 0; j < 4; j++)
#pragma unroll
            for (int e = 0; e < 4; e++) acc[i][j][e] = 0.f;

    float4 ra0, ra1, rb0, rb1;
    // prologue: stage k0 = 0
    ra0 = *(const float4*)(A + (size_t)(m0 + srow)      * DIM + sc4);
    ra1 = *(const float4*)(A + (size_t)(m0 + srow + 64) * DIM + sc4);
    rb0 = *(const float4*)(W + (size_t)(n0 + srow)      * DIM + sc4);
    rb1 = *(const float4*)(W + (size_t)(n0 + srow + 64) * DIM + sc4);
    *(float4*)&As[0][srow][sc4]      = cvt4(ra0);
    *(float4*)&As[0][srow + 64][sc4] = cvt4(ra1);
    *(float4*)&Bs[0][srow][sc4]      = cvt4(rb0);
    *(float4*)&Bs[0][srow + 64][sc4] = cvt4(rb1);
    __syncthreads();

    int cur = 0;
    for (int k0 = 0; k0 < DIM; k0 += 16, cur ^= 1) {
        const bool more = (k0 + 16 < DIM);
        if (more) {
            ra0 = *(const float4*)(A + (size_t)(m0 + srow)      * DIM + k0 + 16 + sc4);
            ra1 = *(const float4*)(A + (size_t)(m0 + srow + 64) * DIM + k0 + 16 + sc4);
            rb0 = *(const float4*)(W + (size_t)(n0 + srow)      * DIM + k0 + 16 + sc4);
            rb1 = *(const float4*)(W + (size_t)(n0 + srow + 64) * DIM + k0 + 16 + sc4);
        }

#pragma unroll
        for (int ks = 0; ks < 2; ks++) {
            const int kk = ks * 8;
            uint32_t af[4][4], bf[4][2];
#pragma unroll
            for (int mt = 0; mt < 4; mt++) {
                int r = wy * 64 + mt * 16;
                af[mt][0] = __float_as_uint(As[cur][r + g][kk + t]);
                af[mt][1] = __float_as_uint(As[cur][r + g + 8][kk + t]);
                af[mt][2] = __float_as_uint(As[cur][r + g][kk + t + 4]);
                af[mt][3] = __float_as_uint(As[cur][r + g + 8][kk + t + 4]);
            }
#pragma unroll
            for (int nt = 0; nt < 4; nt++) {
                int c = wx * 32 + nt * 8;
                bf[nt][0] = __float_as_uint(Bs[cur][c + g][kk + t]);
                bf[nt][1] = __float_as_uint(Bs[cur][c + g][kk + t + 4]);
            }
#pragma unroll
            for (int mt = 0; mt < 4; mt++)
#pragma unroll
                for (int nt = 0; nt < 4; nt++)
                    mma8(acc[mt][nt], af[mt][0], af[mt][1], af[mt][2], af[mt][3],
                         bf[nt][0], bf[nt][1]);
        }

        if (more) {
            *(float4*)&As[cur ^ 1][srow][sc4]      = cvt4(ra0);
            *(float4*)&As[cur ^ 1][srow + 64][sc4] = cvt4(ra1);
            *(float4*)&Bs[cur ^ 1][srow][sc4]      = cvt4(rb0);
            *(float4*)&Bs[cur ^ 1][srow + 64][sc4] = cvt4(rb1);
        }
        __syncthreads();
    }

    float* dstQKV = (MODE == 1) ? ((sel == 0) ? g_Q : ((sel == 1) ? g_K : g_V)) : nullptr;
#pragma unroll
    for (int mt = 0; mt < 4; mt++) {
        int rbase = wy * 64 + mt * 16 + g;
#pragma unroll
        for (int nt = 0; nt < 4; nt++) {
            int cbase = wx * 32 + nt * 8 + 2 * t;
#pragma unroll
            for (int e = 0; e < 4; e++) {
                int gm = m0 + rbase + ((e >= 2) ? 8 : 0);
                int gn = n0 + cbase + (e & 1);
                float v = acc[mt][nt][e];
                if (MODE == 0) {
                    Cext[(size_t)gm * DIM + gn] = v + bias[gn];
                } else {
                    int bb = gm / SEQ, nrow = gm % SEQ;
                    int hh = gn / HDIM, hd = gn % HDIM;
                    dstQKV[(((size_t)bb * NHEAD + hh) * SEQ + nrow) * HDIM + hd] = v;
                }
            }
        }
    }
}

// ---------------- fused causal attention with skewed relative positions ----------------
// srel[r,c] = q_{r-1} . e_{N-(r-c)} for c<r, 0 at c==r (via zero-filled E rows >= N).
// G banded: Gb[r][i] = G[r][63-r+i], i in [0,64). Consumer gather index is then just cc.
#define WQp 68
#define WEp 68
#define GBW 65
#define ATTN_SMEM_FLOATS (65*WQp + 64*WQp + 64*WQp + 128*WEp + 64*GBW)
#define ATTN_SMEM_BYTES  (ATTN_SMEM_FLOATS * 4)

__global__ __launch_bounds__(128, 2)
void attn_kernel(const float* __restrict__ rel)
{
    extern __shared__ float sm[];
    float* sQ  = sm;                    // [65][WQp]  tf32 bits, q rows r0-1..r0+63
    float* sK  = sQ + 65 * WQp;         // [64][WQp]  tf32 bits
    float* sV  = sK + 64 * WQp;         // [64][WQp]  tf32 bits
    float* sE  = sV + 64 * WQp;         // [128][WEp] tf32 bits
    float* sGb = sE + 128 * WEp;        // [64][GBW]  G band / P (warp-private rows)

    // descending qt: longest CTAs (most k-tiles) launch first -> short tail wave
    const int qt = (gridDim.x - 1) - blockIdx.x;   // 31..0
    const int bh = blockIdx.y;          // 0..31
    const int r0 = qt * 64;
    const int b  = bh / NHEAD;
    const int h  = bh % NHEAD;
    const int hcol = h * HDIM;

    const float* Qg = g_Q + (size_t)bh * SEQ * HDIM;
    const float* Kg = g_K + (size_t)bh * SEQ * HDIM;
    const float* Vg = g_V + (size_t)bh * SEQ * HDIM;

    const int tid = threadIdx.x;
    const int w = tid >> 5, lane = tid & 31, g = lane >> 2, t = lane & 3;
    const int rA = w * 16 + g;          // tile-local rows rA and rA+8

    // stage Q rows r0-1 .. r0+63 (row -1 clamped; never consumed), pre-cvt tf32
    for (int idx = tid; idx < 65 * 16; idx += 128) {
        int row = idx >> 4, c4 = (idx & 15) << 2;
        int gr = r0 - 1 + row; if (gr < 0) gr = 0;
        float4 v = *(const float4*)(Qg + (size_t)gr * HDIM + c4);
        float* d = sQ + row * WQp + c4;
        d[0] = f2tf(v.x); d[1] = f2tf(v.y); d[2] = f2tf(v.z); d[3] = f2tf(v.w);
    }
    __syncthreads();

    // persistent A-fragments: aQ = q rows (offset +1), aQp = q_{r-1} rows (offset 0)
    uint32_t aQ[8][4], aQp[8][4];
#pragma unroll
    for (int ks = 0; ks < 8; ks++) {
        int kk = ks * 8;
        aQ[ks][0]  = __float_as_uint(sQ[(1 + rA) * WQp + kk + t]);
        aQ[ks][1]  = __float_as_uint(sQ[(9 + rA) * WQp + kk + t]);
        aQ[ks][2]  = __float_as_uint(sQ[(1 + rA) * WQp + kk + t + 4]);
        aQ[ks][3]  = __float_as_uint(sQ[(9 + rA) * WQp + kk + t + 4]);
        aQp[ks][0] = __float_as_uint(sQ[(rA)     * WQp + kk + t]);
        aQp[ks][1] = __float_as_uint(sQ[(8 + rA) * WQp + kk + t]);
        aQp[ks][2] = __float_as_uint(sQ[(rA)     * WQp + kk + t + 4]);
        aQp[ks][3] = __float_as_uint(sQ[(8 + rA) * WQp + kk + t + 4]);
    }

    float Oacc[8][4];
#pragma unroll
    for (int i = 0; i < 8; i++)
#pragma unroll
        for (int e = 0; e < 4; e++) Oacc[i][e] = 0.f;
    float m0r = -1e30f, m1r = -1e30f;
    float l0r = 0.f,    l1r = 0.f;

    for (int j = 0; j <= qt; j++) {
        const int c0 = j * 64;
        __syncthreads();   // previous iteration's sK/sV/sE readers are done

        // stage K, V tiles (pre-cvt tf32)
        for (int idx = tid; idx < 64 * 16; idx += 128) {
            int row = idx >> 4, c4 = (idx & 15) << 2;
            float4 kv = *(const float4*)(Kg + (size_t)(c0 + row) * HDIM + c4);
            float* dk = sK + row * WQp + c4;
            dk[0] = f2tf(kv.x); dk[1] = f2tf(kv.y); dk[2] = f2tf(kv.z); dk[3] = f2tf(kv.w);
            float4 vv = *(const float4*)(Vg + (size_t)(c0 + row) * HDIM + c4);
            float* dv = sV + row * WQp + c4;
            dv[0] = f2tf(vv.x); dv[1] = f2tf(vv.y); dv[2] = f2tf(vv.z); dv[3] = f2tf(vv.w);
        }
        // stage E window: sE row holds logical e-index elog0+row; rows >= SEQ zero-filled
        const int elog0 = SEQ - r0 + c0 - 63;   // >= 1 always
        for (int idx = tid; idx < 128 * 16; idx += 128) {
            int row = idx >> 4, c4 = (idx & 15) << 2;
            int el = elog0 + row;
            float4 ev = make_float4(0.f, 0.f, 0.f, 0.f);
            if (el < SEQ)
                ev = *(const float4*)(rel + (size_t)(el + (MAXLEN - SEQ)) * DIM + hcol + c4);
            float* de = sE + row * WEp + c4;
            de[0] = f2tf(ev.x); de[1] = f2tf(ev.y); de[2] = f2tf(ev.z); de[3] = f2tf(ev.w);
        }
        __syncthreads();

        // ---- G band = Qprev @ Ewin^T, only the n-tiles this warp's rows consume ----
        // rows 16w..16w+15 need G cols [48-16w, 126-16w] -> nt in [6-2w, 15-2w]
        const int nt0 = 6 - 2 * w;
#pragma unroll
        for (int ntl = 0; ntl < 10; ntl++) {
            const int nt = nt0 + ntl;
            float ga[4] = {0.f, 0.f, 0.f, 0.f};
            const int er = nt * 8 + g;
#pragma unroll
            for (int ks = 0; ks < 8; ks++) {
                int kk = ks * 8;
                uint32_t b0 = __float_as_uint(sE[er * WEp + kk + t]);
                uint32_t b1 = __float_as_uint(sE[er * WEp + kk + t + 4]);
                mma8(ga, aQp[ks][0], aQp[ks][1], aQp[ks][2], aQp[ks][3], b0, b1);
            }
            const int cc = nt * 8 + 2 * t;
            const int i0 = cc + rA - 63;        // band index for row rA
            const int i2 = i0 + 8;              // band index for row rA+8
            if (i0 >= 0     && i0 < 64)     sGb[(rA)     * GBW + i0]     = ga[0];
            if (i0 + 1 >= 0 && i0 + 1 < 64) sGb[(rA)     * GBW + i0 + 1] = ga[1];
            if (i2 >= 0     && i2 < 64)     sGb[(rA + 8) * GBW + i2]     = ga[2];
            if (i2 + 1 >= 0 && i2 + 1 < 64) sGb[(rA + 8) * GBW + i2 + 1] = ga[3];
        }
        __syncwarp();

        // ---- S = Q @ K^T + srel (band gather), mask, scale ----
        float Sreg[8][4];
        float tmax0 = -1e30f, tmax1 = -1e30f;
#pragma unroll
        for (int nt = 0; nt < 8; nt++) {
            float* s = Sreg[nt];
            s[0] = s[1] = s[2] = s[3] = 0.f;
            const int kr = nt * 8 + g;
#pragma unroll
            for (int ks = 0; ks < 8; ks++) {
                int kk = ks * 8;
                uint32_t b0 = __float_as_uint(sK[kr * WQp + kk + t]);
                uint32_t b1 = __float_as_uint(sK[kr * WQp + kk + t + 4]);
                mma8(s, aQ[ks][0], aQ[ks][1], aQ[ks][2], aQ[ks][3], b0, b1);
            }
            const int cc0 = nt * 8 + 2 * t;
            float v;
            v = (s[0] + sGb[rA * GBW + cc0]) * 0.125f;
            if (c0 + cc0 > r0 + rA) v = -1e30f;
            s[0] = v; tmax0 = fmaxf(tmax0, v);

            v = (s[1] + sGb[rA * GBW + cc0 + 1]) * 0.125f;
            if (c0 + cc0 + 1 > r0 + rA) v = -1e30f;
            s[1] = v; tmax0 = fmaxf(tmax0, v);

            v = (s[2] + sGb[(rA + 8) * GBW + cc0]) * 0.125f;
            if (c0 + cc0 > r0 + rA + 8) v = -1e30f;
            s[2] = v; tmax1 = fmaxf(tmax1, v);

            v = (s[3] + sGb[(rA + 8) * GBW + cc0 + 1]) * 0.125f;
            if (c0 + cc0 + 1 > r0 + rA + 8) v = -1e30f;
            s[3] = v; tmax1 = fmaxf(tmax1, v);
        }

        // quad reductions (lanes sharing rows)
        tmax0 = fmaxf(tmax0, __shfl_xor_sync(0xffffffffu, tmax0, 1));
        tmax0 = fmaxf(tmax0, __shfl_xor_sync(0xffffffffu, tmax0, 2));
        tmax1 = fmaxf(tmax1, __shfl_xor_sync(0xffffffffu, tmax1, 1));
        tmax1 = fmaxf(tmax1, __shfl_xor_sync(0xffffffffu, tmax1, 2));

        float mn0 = fmaxf(m0r, tmax0), mn1 = fmaxf(m1r, tmax1);
        float f0 = __expf(m0r - mn0),  f1 = __expf(m1r - mn1);
        float rs0 = 0.f, rs1 = 0.f;
#pragma unroll
        for (int nt = 0; nt < 8; nt++) {
            float* s = Sreg[nt];
            s[0] = __expf(s[0] - mn0); s[1] = __expf(s[1] - mn0);
            s[2] = __expf(s[2] - mn1); s[3] = __expf(s[3] - mn1);
            rs0 += s[0] + s[1];
            rs1 += s[2] + s[3];
        }
        rs0 += __shfl_xor_sync(0xffffffffu, rs0, 1);
        rs0 += __shfl_xor_sync(0xffffffffu, rs0, 2);
        rs1 += __shfl_xor_sync(0xffffffffu, rs1, 1);
        rs1 += __shfl_xor_sync(0xffffffffu, rs1, 2);

        m0r = mn0; m1r = mn1;
        l0r = l0r * f0 + rs0;
        l1r = l1r * f1 + rs1;
#pragma unroll
        for (int dn = 0; dn < 8; dn++) {
            Oacc[dn][0] *= f0; Oacc[dn][1] *= f0;
            Oacc[dn][2] *= f1; Oacc[dn][3] *= f1;
        }

        __syncwarp();   // all band-gather reads done before overwriting with P
#pragma unroll
        for (int nt = 0; nt < 8; nt++) {
            int cc0 = nt * 8 + 2 * t;
            sGb[(rA)     * GBW + cc0]     = f2tf(Sreg[nt][0]);
            sGb[(rA)     * GBW + cc0 + 1] = f2tf(Sreg[nt][1]);
            sGb[(rA + 8) * GBW + cc0]     = f2tf(Sreg[nt][2]);
            sGb[(rA + 8) * GBW + cc0 + 1] = f2tf(Sreg[nt][3]);
        }
        __syncwarp();

        // ---- O += P @ V ----
        uint32_t aP[8][4];
#pragma unroll
        for (int ks = 0; ks < 8; ks++) {
            int kk = ks * 8;
            aP[ks][0] = __float_as_uint(sGb[(rA)     * GBW + kk + t]);
            aP[ks][1] = __float_as_uint(sGb[(rA + 8) * GBW + kk + t]);
            aP[ks][2] = __float_as_uint(sGb[(rA)     * GBW + kk + t + 4]);
            aP[ks][3] = __float_as_uint(sGb[(rA + 8) * GBW + kk + t + 4]);
        }
#pragma unroll
        for (int dn = 0; dn < 8; dn++) {
            const int nb = dn * 8 + g;
#pragma unroll
            for (int ks = 0; ks < 8; ks++) {
                int kk = ks * 8;
                uint32_t b0 = __float_as_uint(sV[(kk + t)     * WQp + nb]);
                uint32_t b1 = __float_as_uint(sV[(kk + t + 4) * WQp + nb]);
                mma8(Oacc[dn], aP[ks][0], aP[ks][1], aP[ks][2], aP[ks][3], b0, b1);
            }
        }
    }

    // ---- normalize and write O in [b][n][h*HD+hd] layout ----
    float inv0 = 1.f / l0r, inv1 = 1.f / l1r;
    float* Og = g_O + (size_t)b * SEQ * DIM + (size_t)r0 * DIM + hcol;
#pragma unroll
    for (int dn = 0; dn < 8; dn++) {
        int d0 = dn * 8 + 2 * t;
        Og[(size_t)(rA)     * DIM + d0]     = Oacc[dn][0] * inv0;
        Og[(size_t)(rA)     * DIM + d0 + 1] = Oacc[dn][1] * inv0;
        Og[(size_t)(rA + 8) * DIM + d0]     = Oacc[dn][2] * inv1;
        Og[(size_t)(rA + 8) * DIM + d0 + 1] = Oacc[dn][3] * inv1;
    }
}

// ---------------- launch ----------------
extern "C" void kernel_launch(void* const* d_in, const int* in_sizes, int n_in,
                              void* d_out, int out_size)
{
    const float* x   = (const float*)d_in[0];
    const float* Wq  = (const float*)d_in[1];
    const float* Wk  = (const float*)d_in[2];
    const float* Wv  = (const float*)d_in[3];
    const float* Wp  = (const float*)d_in[4];
    const float* bp  = (const float*)d_in[5];
    const float* rel = (const float*)d_in[6];
    float* out = (float*)d_out;

    cudaFuncSetAttribute(attn_kernel,
                         cudaFuncAttributeMaxDynamicSharedMemorySize,
                         ATTN_SMEM_BYTES);

    gemm_tn<1><<<dim3(DIM / 128, BN / 128, 3), 256>>>(x, Wq, Wk, Wv, nullptr, nullptr);
    attn_kernel<<<dim3(SEQ / 64, BATCH * NHEAD), 128, ATTN_SMEM_BYTES>>>(rel);
    gemm_tn<0><<<dim3(DIM / 128, BN / 128), 256>>>(nullptr, Wp, nullptr, nullptr, bp, out);
}

// round 11
// speedup vs baseline: 3.3702x; 1.0564x over previous
#include <cuda_runtime.h>
#include <stdint.h>

#define BATCH   2
#define SEQ     2048
#define DIM     1024
#define NHEAD   16
#define HDIM    64
#define MAXLEN  2048
#define BN      (BATCH*SEQ)

// ---------------- scratch (device globals; allocation is forbidden) ----------------
__device__ float g_Q[(size_t)BATCH * NHEAD * SEQ * HDIM];   // [(b*H+h)][n][hd]
__device__ float g_K[(size_t)BATCH * NHEAD * SEQ * HDIM];
__device__ float g_V[(size_t)BATCH * NHEAD * SEQ * HDIM];
__device__ float g_O[(size_t)BATCH * SEQ * DIM];            // [b][n][h*HD+hd]

// ---------------- helpers ----------------
__device__ __forceinline__ uint32_t f2t(float f) {
    uint32_t u;
    asm("cvt.rna.tf32.f32 %0, %1;" : "=r"(u) : "f"(f));
    return u;
}
__device__ __forceinline__ float f2tf(float f) {
    return __uint_as_float(f2t(f));
}
__device__ __forceinline__ void mma8(float c[4],
                                     uint32_t a0, uint32_t a1, uint32_t a2, uint32_t a3,
                                     uint32_t b0, uint32_t b1) {
    asm volatile(
        "mma.sync.aligned.m16n8k8.row.col.f32.tf32.tf32.f32 "
        "{%0,%1,%2,%3},{%4,%5,%6,%7},{%8,%9},{%0,%1,%2,%3};"
        : "+f"(c[0]), "+f"(c[1]), "+f"(c[2]), "+f"(c[3])
        : "r"(a0), "r"(a1), "r"(a2), "r"(a3), "r"(b0), "r"(b1));
}
#define U(x) __float_as_uint(x)

// ---------------- GEMM: C[m,n] = sum_k A[m,k] * W[n,k], 1x tf32 ----------------
// Smem layout per 16-k block, per row (16 floats, no pad):
//   k stored in permuted order p(k) = (k%4)*4 + k/4, as 4 chunks of 4 words,
//   chunk XOR-swizzled: phys(row, p) = row*16 + 4*((p>>2) ^ ((row>>1)&3)) + (p&3)
// => lane t's fragment k-set {t, t+4, t+8, t+12} = chunk t: ONE conflict-free LDS.128
//    covering BOTH ks-steps; staging = 4 conflict-free STS.32 per float4.
// MODE 0: A = g_O, C = Cext[m*DIM+n] + bias[n]
// MODE 1: A = Aext(x), W = {W0,W1,W2}[blockIdx.z], scatter to g_{Q,K,V}
template<int MODE>
__global__ __launch_bounds__(256, 2)
void gemm_tn(const float* __restrict__ Aext,
             const float* __restrict__ W0, const float* __restrict__ W1,
             const float* __restrict__ W2,
             const float* __restrict__ bias, float* __restrict__ Cext)
{
    __align__(16) __shared__ float As[2][128 * 16];   // tf32 bits, swizzled
    __align__(16) __shared__ float Bs[2][128 * 16];

    const int sel = (MODE == 1) ? blockIdx.z : 0;
    const float* W = (MODE == 0) ? W0 : ((sel == 0) ? W0 : (sel == 1) ? W1 : W2);
    const float* A = (MODE == 0) ? (const float*)g_O : Aext;

    const int m0 = blockIdx.y * 128;
    const int n0 = blockIdx.x * 128;
    const int tid = threadIdx.x;
    const int w = tid >> 5, lane = tid & 31, g = lane >> 2, t = lane & 3;
    const int wy = w >> 2, wx = w & 3;   // 2x4 warp grid; warp tile 64x32

    const int srow = tid >> 2;           // 0..63 (staging row; +64 for second row)
    const int sc   = tid & 3;            // gmem k-chunk 4*sc .. 4*sc+3
    const int sxb  = (srow >> 1) & 3;    // swizzle bits (same for srow and srow+64)

    float acc[4][4][4];
#pragma unroll
    for (int i = 0; i < 4; i++)
#pragma unroll
        for (int j = 0; j < 4; j++)
#pragma unroll
            for (int e = 0; e < 4; e++) acc[i][j][e] = 0.f;

    // staging store: value v = gmem k (4*sc+i) -> kperm = 4*i + sc -> chunk i, word sc
    auto stage = [&](float* S, int row, float4 v) {
        float* base = S + row * 16 + sc;
        base[4 * (0 ^ sxb)] = f2tf(v.x);
        base[4 * (1 ^ sxb)] = f2tf(v.y);
        base[4 * (2 ^ sxb)] = f2tf(v.z);
        base[4 * (3 ^ sxb)] = f2tf(v.w);
    };

    float4 ra0, ra1, rb0, rb1;
    // prologue: stage k0 = 0
    ra0 = *(const float4*)(A + (size_t)(m0 + srow)      * DIM + 4 * sc);
    ra1 = *(const float4*)(A + (size_t)(m0 + srow + 64) * DIM + 4 * sc);
    rb0 = *(const float4*)(W + (size_t)(n0 + srow)      * DIM + 4 * sc);
    rb1 = *(const float4*)(W + (size_t)(n0 + srow + 64) * DIM + 4 * sc);
    stage(As[0], srow,      ra0);
    stage(As[0], srow + 64, ra1);
    stage(Bs[0], srow,      rb0);
    stage(Bs[0], srow + 64, rb1);
    __syncthreads();

    int cur = 0;
    for (int k0 = 0; k0 < DIM; k0 += 16, cur ^= 1) {
        const bool more = (k0 + 16 < DIM);
        if (more) {
            ra0 = *(const float4*)(A + (size_t)(m0 + srow)      * DIM + k0 + 16 + 4 * sc);
            ra1 = *(const float4*)(A + (size_t)(m0 + srow + 64) * DIM + k0 + 16 + 4 * sc);
            rb0 = *(const float4*)(W + (size_t)(n0 + srow)      * DIM + k0 + 16 + 4 * sc);
            rb1 = *(const float4*)(W + (size_t)(n0 + srow + 64) * DIM + k0 + 16 + 4 * sc);
        }

        // fragment loads: one LDS.128 per row covers all 16 k (both ks-steps)
        // f.x = k(t), f.y = k(t+4), f.z = k(t+8), f.w = k(t+12)
        float4 fa[4][2], fb[4];
#pragma unroll
        for (int mt = 0; mt < 4; mt++) {
            int r = wy * 64 + mt * 16 + g;
            fa[mt][0] = *(float4*)&As[cur][r * 16 + 4 * (t ^ ((r >> 1) & 3))];
            int r2 = r + 8;
            fa[mt][1] = *(float4*)&As[cur][r2 * 16 + 4 * (t ^ ((r2 >> 1) & 3))];
        }
#pragma unroll
        for (int nt = 0; nt < 4; nt++) {
            int c = wx * 32 + nt * 8 + g;
            fb[nt] = *(float4*)&Bs[cur][c * 16 + 4 * (t ^ ((c >> 1) & 3))];
        }

#pragma unroll
        for (int mt = 0; mt < 4; mt++)
#pragma unroll
            for (int nt = 0; nt < 4; nt++) {
                // ks = 0 : k in {t, t+4}
                mma8(acc[mt][nt], U(fa[mt][0].x), U(fa[mt][1].x),
                                  U(fa[mt][0].y), U(fa[mt][1].y),
                                  U(fb[nt].x),    U(fb[nt].y));
                // ks = 1 : k in {t+8, t+12}
                mma8(acc[mt][nt], U(fa[mt][0].z), U(fa[mt][1].z),
                                  U(fa[mt][0].w), U(fa[mt][1].w),
                                  U(fb[nt].z),    U(fb[nt].w));
            }

        if (more) {
            stage(As[cur ^ 1], srow,      ra0);
            stage(As[cur ^ 1], srow + 64, ra1);
            stage(Bs[cur ^ 1], srow,      rb0);
            stage(Bs[cur ^ 1], srow + 64, rb1);
        }
        __syncthreads();
    }

    float* dstQKV = (MODE == 1) ? ((sel == 0) ? g_Q : ((sel == 1) ? g_K : g_V)) : nullptr;
#pragma unroll
    for (int mt = 0; mt < 4; mt++) {
        int rbase = wy * 64 + mt * 16 + g;
#pragma unroll
        for (int nt = 0; nt < 4; nt++) {
            int cbase = wx * 32 + nt * 8 + 2 * t;
#pragma unroll
            for (int e = 0; e < 4; e++) {
                int gm = m0 + rbase + ((e >= 2) ? 8 : 0);
                int gn = n0 + cbase + (e & 1);
                float v = acc[mt][nt][e];
                if (MODE == 0) {
                    Cext[(size_t)gm * DIM + gn] = v + bias[gn];
                } else {
                    int bb = gm / SEQ, nrow = gm % SEQ;
                    int hh = gn / HDIM, hd = gn % HDIM;
                    dstQKV[(((size_t)bb * NHEAD + hh) * SEQ + nrow) * HDIM + hd] = v;
                }
            }
        }
    }
}

// ---------------- fused causal attention with skewed relative positions ----------------
// srel[r,c] = q_{r-1} . e_{N-(r-c)} for c<r, 0 at c==r (via zero-filled E rows >= N).
// G banded: Gb[r][i] = G[r][63-r+i], i in [0,64). Consumer gather index is then just cc.
#define WQp 68
#define WEp 68
#define GBW 65
#define ATTN_SMEM_FLOATS (65*WQp + 64*WQp + 64*WQp + 128*WEp + 64*GBW)
#define ATTN_SMEM_BYTES  (ATTN_SMEM_FLOATS * 4)

__global__ __launch_bounds__(128, 2)
void attn_kernel(const float* __restrict__ rel)
{
    extern __shared__ float sm[];
    float* sQ  = sm;                    // [65][WQp]  tf32 bits, q rows r0-1..r0+63
    float* sK  = sQ + 65 * WQp;         // [64][WQp]  tf32 bits
    float* sV  = sK + 64 * WQp;         // [64][WQp]  tf32 bits
    float* sE  = sV + 64 * WQp;         // [128][WEp] tf32 bits
    float* sGb = sE + 128 * WEp;        // [64][GBW]  G band / P (warp-private rows)

    // descending qt: longest CTAs (most k-tiles) launch first -> short tail wave
    const int qt = (gridDim.x - 1) - blockIdx.x;   // 31..0
    const int bh = blockIdx.y;          // 0..31
    const int r0 = qt * 64;
    const int b  = bh / NHEAD;
    const int h  = bh % NHEAD;
    const int hcol = h * HDIM;

    const float* Qg = g_Q + (size_t)bh * SEQ * HDIM;
    const float* Kg = g_K + (size_t)bh * SEQ * HDIM;
    const float* Vg = g_V + (size_t)bh * SEQ * HDIM;

    const int tid = threadIdx.x;
    const int w = tid >> 5, lane = tid & 31, g = lane >> 2, t = lane & 3;
    const int rA = w * 16 + g;          // tile-local rows rA and rA+8

    // stage Q rows r0-1 .. r0+63 (row -1 clamped; never consumed), pre-cvt tf32
    for (int idx = tid; idx < 65 * 16; idx += 128) {
        int row = idx >> 4, c4 = (idx & 15) << 2;
        int gr = r0 - 1 + row; if (gr < 0) gr = 0;
        float4 v = *(const float4*)(Qg + (size_t)gr * HDIM + c4);
        float* d = sQ + row * WQp + c4;
        d[0] = f2tf(v.x); d[1] = f2tf(v.y); d[2] = f2tf(v.z); d[3] = f2tf(v.w);
    }
    __syncthreads();

    // persistent A-fragments: aQ = q rows (offset +1), aQp = q_{r-1} rows (offset 0)
    uint32_t aQ[8][4], aQp[8][4];
#pragma unroll
    for (int ks = 0; ks < 8; ks++) {
        int kk = ks * 8;
        aQ[ks][0]  = __float_as_uint(sQ[(1 + rA) * WQp + kk + t]);
        aQ[ks][1]  = __float_as_uint(sQ[(9 + rA) * WQp + kk + t]);
        aQ[ks][2]  = __float_as_uint(sQ[(1 + rA) * WQp + kk + t + 4]);
        aQ[ks][3]  = __float_as_uint(sQ[(9 + rA) * WQp + kk + t + 4]);
        aQp[ks][0] = __float_as_uint(sQ[(rA)     * WQp + kk + t]);
        aQp[ks][1] = __float_as_uint(sQ[(8 + rA) * WQp + kk + t]);
        aQp[ks][2] = __float_as_uint(sQ[(rA)     * WQp + kk + t + 4]);
        aQp[ks][3] = __float_as_uint(sQ[(8 + rA) * WQp + kk + t + 4]);
    }

    float Oacc[8][4];
#pragma unroll
    for (int i = 0; i < 8; i++)
#pragma unroll
        for (int e = 0; e < 4; e++) Oacc[i][e] = 0.f;
    float m0r = -1e30f, m1r = -1e30f;
    float l0r = 0.f,    l1r = 0.f;

    for (int j = 0; j <= qt; j++) {
        const int c0 = j * 64;
        __syncthreads();   // previous iteration's sK/sV/sE readers are done

        // stage K, V tiles (pre-cvt tf32)
        for (int idx = tid; idx < 64 * 16; idx += 128) {
            int row = idx >> 4, c4 = (idx & 15) << 2;
            float4 kv = *(const float4*)(Kg + (size_t)(c0 + row) * HDIM + c4);
            float* dk = sK + row * WQp + c4;
            dk[0] = f2tf(kv.x); dk[1] = f2tf(kv.y); dk[2] = f2tf(kv.z); dk[3] = f2tf(kv.w);
            float4 vv = *(const float4*)(Vg + (size_t)(c0 + row) * HDIM + c4);
            float* dv = sV + row * WQp + c4;
            dv[0] = f2tf(vv.x); dv[1] = f2tf(vv.y); dv[2] = f2tf(vv.z); dv[3] = f2tf(vv.w);
        }
        // stage E window: sE row holds logical e-index elog0+row; rows >= SEQ zero-filled
        const int elog0 = SEQ - r0 + c0 - 63;   // >= 1 always
        for (int idx = tid; idx < 128 * 16; idx += 128) {
            int row = idx >> 4, c4 = (idx & 15) << 2;
            int el = elog0 + row;
            float4 ev = make_float4(0.f, 0.f, 0.f, 0.f);
            if (el < SEQ)
                ev = *(const float4*)(rel + (size_t)(el + (MAXLEN - SEQ)) * DIM + hcol + c4);
            float* de = sE + row * WEp + c4;
            de[0] = f2tf(ev.x); de[1] = f2tf(ev.y); de[2] = f2tf(ev.z); de[3] = f2tf(ev.w);
        }
        __syncthreads();

        // ---- G band = Qprev @ Ewin^T, only the n-tiles this warp's rows consume ----
        // rows 16w..16w+15 need G cols [48-16w, 126-16w] -> nt in [6-2w, 15-2w]
        const int nt0 = 6 - 2 * w;
#pragma unroll
        for (int ntl = 0; ntl < 10; ntl++) {
            const int nt = nt0 + ntl;
            float ga[4] = {0.f, 0.f, 0.f, 0.f};
            const int er = nt * 8 + g;
#pragma unroll
            for (int ks = 0; ks < 8; ks++) {
                int kk = ks * 8;
                uint32_t b0 = __float_as_uint(sE[er * WEp + kk + t]);
                uint32_t b1 = __float_as_uint(sE[er * WEp + kk + t + 4]);
                mma8(ga, aQp[ks][0], aQp[ks][1], aQp[ks][2], aQp[ks][3], b0, b1);
            }
            const int cc = nt * 8 + 2 * t;
            const int i0 = cc + rA - 63;        // band index for row rA
            const int i2 = i0 + 8;              // band index for row rA+8
            if (i0 >= 0     && i0 < 64)     sGb[(rA)     * GBW + i0]     = ga[0];
            if (i0 + 1 >= 0 && i0 + 1 < 64) sGb[(rA)     * GBW + i0 + 1] = ga[1];
            if (i2 >= 0     && i2 < 64)     sGb[(rA + 8) * GBW + i2]     = ga[2];
            if (i2 + 1 >= 0 && i2 + 1 < 64) sGb[(rA + 8) * GBW + i2 + 1] = ga[3];
        }
        __syncwarp();

        // ---- S = Q @ K^T + srel (band gather), mask, scale ----
        float Sreg[8][4];
        float tmax0 = -1e30f, tmax1 = -1e30f;
#pragma unroll
        for (int nt = 0; nt < 8; nt++) {
            float* s = Sreg[nt];
            s[0] = s[1] = s[2] = s[3] = 0.f;
            const int kr = nt * 8 + g;
#pragma unroll
            for (int ks = 0; ks < 8; ks++) {
                int kk = ks * 8;
                uint32_t b0 = __float_as_uint(sK[kr * WQp + kk + t]);
                uint32_t b1 = __float_as_uint(sK[kr * WQp + kk + t + 4]);
                mma8(s, aQ[ks][0], aQ[ks][1], aQ[ks][2], aQ[ks][3], b0, b1);
            }
            const int cc0 = nt * 8 + 2 * t;
            float v;
            v = (s[0] + sGb[rA * GBW + cc0]) * 0.125f;
            if (c0 + cc0 > r0 + rA) v = -1e30f;
            s[0] = v; tmax0 = fmaxf(tmax0, v);

            v = (s[1] + sGb[rA * GBW + cc0 + 1]) * 0.125f;
            if (c0 + cc0 + 1 > r0 + rA) v = -1e30f;
            s[1] = v; tmax0 = fmaxf(tmax0, v);

            v = (s[2] + sGb[(rA + 8) * GBW + cc0]) * 0.125f;
            if (c0 + cc0 > r0 + rA + 8) v = -1e30f;
            s[2] = v; tmax1 = fmaxf(tmax1, v);

            v = (s[3] + sGb[(rA + 8) * GBW + cc0 + 1]) * 0.125f;
            if (c0 + cc0 + 1 > r0 + rA + 8) v = -1e30f;
            s[3] = v; tmax1 = fmaxf(tmax1, v);
        }

        // quad reductions (lanes sharing rows)
        tmax0 = fmaxf(tmax0, __shfl_xor_sync(0xffffffffu, tmax0, 1));
        tmax0 = fmaxf(tmax0, __shfl_xor_sync(0xffffffffu, tmax0, 2));
        tmax1 = fmaxf(tmax1, __shfl_xor_sync(0xffffffffu, tmax1, 1));
        tmax1 = fmaxf(tmax1, __shfl_xor_sync(0xffffffffu, tmax1, 2));

        float mn0 = fmaxf(m0r, tmax0), mn1 = fmaxf(m1r, tmax1);
        float f0 = __expf(m0r - mn0),  f1 = __expf(m1r - mn1);
        float rs0 = 0.f, rs1 = 0.f;
#pragma unroll
        for (int nt = 0; nt < 8; nt++) {
            float* s = Sreg[nt];
            s[0] = __expf(s[0] - mn0); s[1] = __expf(s[1] - mn0);
            s[2] = __expf(s[2] - mn1); s[3] = __expf(s[3] - mn1);
            rs0 += s[0] + s[1];
            rs1 += s[2] + s[3];
        }
        rs0 += __shfl_xor_sync(0xffffffffu, rs0, 1);
        rs0 += __shfl_xor_sync(0xffffffffu, rs0, 2);
        rs1 += __shfl_xor_sync(0xffffffffu, rs1, 1);
        rs1 += __shfl_xor_sync(0xffffffffu, rs1, 2);

        m0r = mn0; m1r = mn1;
        l0r = l0r * f0 + rs0;
        l1r = l1r * f1 + rs1;
#pragma unroll
        for (int dn = 0; dn < 8; dn++) {
            Oacc[dn][0] *= f0; Oacc[dn][1] *= f0;
            Oacc[dn][2] *= f1; Oacc[dn][3] *= f1;
        }

        __syncwarp();   // all band-gather reads done before overwriting with P
#pragma unroll
        for (int nt = 0; nt < 8; nt++) {
            int cc0 = nt * 8 + 2 * t;
            sGb[(rA)     * GBW + cc0]     = f2tf(Sreg[nt][0]);
            sGb[(rA)     * GBW + cc0 + 1] = f2tf(Sreg[nt][1]);
            sGb[(rA + 8) * GBW + cc0]     = f2tf(Sreg[nt][2]);
            sGb[(rA + 8) * GBW + cc0 + 1] = f2tf(Sreg[nt][3]);
        }
        __syncwarp();

        // ---- O += P @ V ----
        uint32_t aP[8][4];
#pragma unroll
        for (int ks = 0; ks < 8; ks++) {
            int kk = ks * 8;
            aP[ks][0] = __float_as_uint(sGb[(rA)     * GBW + kk + t]);
            aP[ks][1] = __float_as_uint(sGb[(rA + 8) * GBW + kk + t]);
            aP[ks][2] = __float_as_uint(sGb[(rA)     * GBW + kk + t + 4]);
            aP[ks][3] = __float_as_uint(sGb[(rA + 8) * GBW + kk + t + 4]);
        }
#pragma unroll
        for (int dn = 0; dn < 8; dn++) {
            const int nb = dn * 8 + g;
#pragma unroll
            for (int ks = 0; ks < 8; ks++) {
                int kk = ks * 8;
                uint32_t b0 = __float_as_uint(sV[(kk + t)     * WQp + nb]);
                uint32_t b1 = __float_as_uint(sV[(kk + t + 4) * WQp + nb]);
                mma8(Oacc[dn], aP[ks][0], aP[ks][1], aP[ks][2], aP[ks][3], b0, b1);
            }
        }
    }

    // ---- normalize and write O in [b][n][h*HD+hd] layout ----
    float inv0 = 1.f / l0r, inv1 = 1.f / l1r;
    float* Og = g_O + (size_t)b * SEQ * DIM + (size_t)r0 * DIM + hcol;
#pragma unroll
    for (int dn = 0; dn < 8; dn++) {
        int d0 = dn * 8 + 2 * t;
        Og[(size_t)(rA)     * DIM + d0]     = Oacc[dn][0] * inv0;
        Og[(size_t)(rA)     * DIM + d0 + 1] = Oacc[dn][1] * inv0;
        Og[(size_t)(rA + 8) * DIM + d0]     = Oacc[dn][2] * inv1;
        Og[(size_t)(rA + 8) * DIM + d0 + 1] = Oacc[dn][3] * inv1;
    }
}

// ---------------- launch ----------------
extern "C" void kernel_launch(void* const* d_in, const int* in_sizes, int n_in,
                              void* d_out, int out_size)
{
    const float* x   = (const float*)d_in[0];
    const float* Wq  = (const float*)d_in[1];
    const float* Wk  = (const float*)d_in[2];
    const float* Wv  = (const float*)d_in[3];
    const float* Wp  = (const float*)d_in[4];
    const float* bp  = (const float*)d_in[5];
    const float* rel = (const float*)d_in[6];
    float* out = (float*)d_out;

    cudaFuncSetAttribute(attn_kernel,
                         cudaFuncAttributeMaxDynamicSharedMemorySize,
                         ATTN_SMEM_BYTES);

    gemm_tn<1><<<dim3(DIM / 128, BN / 128, 3), 256>>>(x, Wq, Wk, Wv, nullptr, nullptr);
    attn_kernel<<<dim3(SEQ / 64, BATCH * NHEAD), 128, ATTN_SMEM_BYTES>>>(rel);
    gemm_tn<0><<<dim3(DIM / 128, BN / 128), 256>>>(nullptr, Wp, nullptr, nullptr, bp, out);
}

// round 12
// speedup vs baseline: 3.4019x; 1.0094x over previous
#include <cuda_runtime.h>
#include <stdint.h>

#define BATCH   2
#define SEQ     2048
#define DIM     1024
#define NHEAD   16
#define HDIM    64
#define MAXLEN  2048
#define BN      (BATCH*SEQ)

// ---------------- scratch (device globals; allocation is forbidden) ----------------
__device__ float g_Q[(size_t)BATCH * NHEAD * SEQ * HDIM];   // [(b*H+h)][n][hd]
__device__ float g_K[(size_t)BATCH * NHEAD * SEQ * HDIM];
__device__ float g_V[(size_t)BATCH * NHEAD * SEQ * HDIM];
__device__ float g_O[(size_t)BATCH * SEQ * DIM];            // [b][n][h*HD+hd]

// ---------------- helpers ----------------
__device__ __forceinline__ uint32_t f2t(float f) {
    uint32_t u;
    asm("cvt.rna.tf32.f32 %0, %1;" : "=r"(u) : "f"(f));
    return u;
}
__device__ __forceinline__ float f2tf(float f) {
    return __uint_as_float(f2t(f));
}
__device__ __forceinline__ void mma8(float c[4],
                                     uint32_t a0, uint32_t a1, uint32_t a2, uint32_t a3,
                                     uint32_t b0, uint32_t b1) {
    asm volatile(
        "mma.sync.aligned.m16n8k8.row.col.f32.tf32.tf32.f32 "
        "{%0,%1,%2,%3},{%4,%5,%6,%7},{%8,%9},{%0,%1,%2,%3};"
        : "+f"(c[0]), "+f"(c[1]), "+f"(c[2]), "+f"(c[3])
        : "r"(a0), "r"(a1), "r"(a2), "r"(a3), "r"(b0), "r"(b1));
}
#define U(x) __float_as_uint(x)

// chunk swizzle for 64-word permuted rows (bit2 = row&1 restores bank splay)
__device__ __forceinline__ int swz(int row) {
    return ((row & 1) << 2) | ((row >> 1) & 3);
}
// store float4 holding gmem k = c4..c4+3 into a permuted 64-word row
// layout: word(k) = 4*((4*(k>>4) + (k&3)) ^ s) + ((k&15)>>2)
__device__ __forceinline__ void stash_perm(float* rowp, int c4, float4 v, int s) {
    int a4 = 4 * (c4 >> 4);
    int wd = (c4 & 15) >> 2;
    rowp[4 * ((a4 + 0) ^ s) + wd] = v.x;
    rowp[4 * ((a4 + 1) ^ s) + wd] = v.y;
    rowp[4 * ((a4 + 2) ^ s) + wd] = v.z;
    rowp[4 * ((a4 + 3) ^ s) + wd] = v.w;
}
// one LDS.128: (x,y,z,w) = k(16kb+t), k(16kb+t+4), k(16kb+t+8), k(16kb+t+12)
__device__ __forceinline__ float4 frag4(const float* S, int stride, int row, int kb, int t) {
    return *(const float4*)&S[row * stride + 4 * ((4 * kb + t) ^ swz(row))];
}

// ---------------- GEMM: C[m,n] = sum_k A[m,k] * W[n,k], 1x tf32 ----------------
// (unchanged from R11: permuted-k + XOR swizzle, double-buffered)
template<int MODE>
__global__ __launch_bounds__(256, 2)
void gemm_tn(const float* __restrict__ Aext,
             const float* __restrict__ W0, const float* __restrict__ W1,
             const float* __restrict__ W2,
             const float* __restrict__ bias, float* __restrict__ Cext)
{
    __align__(16) __shared__ float As[2][128 * 16];   // tf32 bits, swizzled
    __align__(16) __shared__ float Bs[2][128 * 16];

    const int sel = (MODE == 1) ? blockIdx.z : 0;
    const float* W = (MODE == 0) ? W0 : ((sel == 0) ? W0 : (sel == 1) ? W1 : W2);
    const float* A = (MODE == 0) ? (const float*)g_O : Aext;

    const int m0 = blockIdx.y * 128;
    const int n0 = blockIdx.x * 128;
    const int tid = threadIdx.x;
    const int w = tid >> 5, lane = tid & 31, g = lane >> 2, t = lane & 3;
    const int wy = w >> 2, wx = w & 3;   // 2x4 warp grid; warp tile 64x32

    const int srow = tid >> 2;
    const int sc   = tid & 3;
    const int sxb  = (srow >> 1) & 3;

    float acc[4][4][4];
#pragma unroll
    for (int i = 0; i < 4; i++)
#pragma unroll
        for (int j = 0; j < 4; j++)
#pragma unroll
            for (int e = 0; e < 4; e++) acc[i][j][e] = 0.f;

    auto stage = [&](float* S, int row, float4 v) {
        float* base = S + row * 16 + sc;
        base[4 * (0 ^ sxb)] = f2tf(v.x);
        base[4 * (1 ^ sxb)] = f2tf(v.y);
        base[4 * (2 ^ sxb)] = f2tf(v.z);
        base[4 * (3 ^ sxb)] = f2tf(v.w);
    };

    float4 ra0, ra1, rb0, rb1;
    ra0 = *(const float4*)(A + (size_t)(m0 + srow)      * DIM + 4 * sc);
    ra1 = *(const float4*)(A + (size_t)(m0 + srow + 64) * DIM + 4 * sc);
    rb0 = *(const float4*)(W + (size_t)(n0 + srow)      * DIM + 4 * sc);
    rb1 = *(const float4*)(W + (size_t)(n0 + srow + 64) * DIM + 4 * sc);
    stage(As[0], srow,      ra0);
    stage(As[0], srow + 64, ra1);
    stage(Bs[0], srow,      rb0);
    stage(Bs[0], srow + 64, rb1);
    __syncthreads();

    int cur = 0;
    for (int k0 = 0; k0 < DIM; k0 += 16, cur ^= 1) {
        const bool more = (k0 + 16 < DIM);
        if (more) {
            ra0 = *(const float4*)(A + (size_t)(m0 + srow)      * DIM + k0 + 16 + 4 * sc);
            ra1 = *(const float4*)(A + (size_t)(m0 + srow + 64) * DIM + k0 + 16 + 4 * sc);
            rb0 = *(const float4*)(W + (size_t)(n0 + srow)      * DIM + k0 + 16 + 4 * sc);
            rb1 = *(const float4*)(W + (size_t)(n0 + srow + 64) * DIM + k0 + 16 + 4 * sc);
        }

        float4 fa[4][2], fb[4];
#pragma unroll
        for (int mt = 0; mt < 4; mt++) {
            int r = wy * 64 + mt * 16 + g;
            fa[mt][0] = *(float4*)&As[cur][r * 16 + 4 * (t ^ ((r >> 1) & 3))];
            int r2 = r + 8;
            fa[mt][1] = *(float4*)&As[cur][r2 * 16 + 4 * (t ^ ((r2 >> 1) & 3))];
        }
#pragma unroll
        for (int nt = 0; nt < 4; nt++) {
            int c = wx * 32 + nt * 8 + g;
            fb[nt] = *(float4*)&Bs[cur][c * 16 + 4 * (t ^ ((c >> 1) & 3))];
        }

#pragma unroll
        for (int mt = 0; mt < 4; mt++)
#pragma unroll
            for (int nt = 0; nt < 4; nt++) {
                mma8(acc[mt][nt], U(fa[mt][0].x), U(fa[mt][1].x),
                                  U(fa[mt][0].y), U(fa[mt][1].y),
                                  U(fb[nt].x),    U(fb[nt].y));
                mma8(acc[mt][nt], U(fa[mt][0].z), U(fa[mt][1].z),
                                  U(fa[mt][0].w), U(fa[mt][1].w),
                                  U(fb[nt].z),    U(fb[nt].w));
            }

        if (more) {
            stage(As[cur ^ 1], srow,      ra0);
            stage(As[cur ^ 1], srow + 64, ra1);
            stage(Bs[cur ^ 1], srow,      rb0);
            stage(Bs[cur ^ 1], srow + 64, rb1);
        }
        __syncthreads();
    }

    float* dstQKV = (MODE == 1) ? ((sel == 0) ? g_Q : ((sel == 1) ? g_K : g_V)) : nullptr;
#pragma unroll
    for (int mt = 0; mt < 4; mt++) {
        int rbase = wy * 64 + mt * 16 + g;
#pragma unroll
        for (int nt = 0; nt < 4; nt++) {
            int cbase = wx * 32 + nt * 8 + 2 * t;
#pragma unroll
            for (int e = 0; e < 4; e++) {
                int gm = m0 + rbase + ((e >= 2) ? 8 : 0);
                int gn = n0 + cbase + (e & 1);
                float v = acc[mt][nt][e];
                if (MODE == 0) {
                    Cext[(size_t)gm * DIM + gn] = v + bias[gn];
                } else {
                    int bb = gm / SEQ, nrow = gm % SEQ;
                    int hh = gn / HDIM, hd = gn % HDIM;
                    dstQKV[(((size_t)bb * NHEAD + hh) * SEQ + nrow) * HDIM + hd] = v;
                }
            }
        }
    }
}

// ---------------- fused causal attention with skewed relative positions ----------------
// srel[r,c] = q_{r-1} . e_{N-(r-c)} for c<r, 0 at c==r (via zero-filled E rows >= N).
// sQ/sK/sE: permuted 64-word rows (4x LDS.128 per fragment row).
// sE: 128-row ring buffer; only 64 new rows staged per k-tile (phys = logical ^ ((j&1)<<6)).
// P: stored permuted into the dead sQ region (aP via 8x LDS.128).
// G band in sGb (stride 65, scalar gather) unchanged.
#define WVp 68
#define GBW 65
#define ATTN_SMEM_FLOATS (65*64 + 64*64 + 64*WVp + 128*64 + 64*GBW)
#define ATTN_SMEM_BYTES  (ATTN_SMEM_FLOATS * 4)

__global__ __launch_bounds__(128, 2)
void attn_kernel(const float* __restrict__ rel)
{
    extern __shared__ float sm[];
    float* sQ  = sm;                    // [65][64] perm tf32; reused as P after init
    float* sK  = sQ + 65 * 64;          // [64][64] perm raw fp32
    float* sV  = sK + 64 * 64;          // [64][WVp] tf32 (scalar reads)
    float* sE  = sV + 64 * WVp;         // [128][64] perm raw fp32, ring
    float* sGb = sE + 128 * 64;         // [64][GBW] G band (scalar)
    float* sP  = sQ;                    // P region: [64][64] perm tf32

    const int qt = (gridDim.x - 1) - blockIdx.x;   // 31..0 (long CTAs first)
    const int bh = blockIdx.y;
    const int r0 = qt * 64;
    const int b  = bh / NHEAD;
    const int h  = bh % NHEAD;
    const int hcol = h * HDIM;

    const float* Qg = g_Q + (size_t)bh * SEQ * HDIM;
    const float* Kg = g_K + (size_t)bh * SEQ * HDIM;
    const float* Vg = g_V + (size_t)bh * SEQ * HDIM;

    const int tid = threadIdx.x;
    const int w = tid >> 5, lane = tid & 31, g = lane >> 2, t = lane & 3;
    const int rA = w * 16 + g;          // tile-local rows rA and rA+8

    // ---- stage Q rows r0-1 .. r0+63 (row -1 clamped; never consumed), perm + cvt ----
    for (int idx = tid; idx < 65 * 16; idx += 128) {
        int row = idx >> 4, c4 = (idx & 15) << 2;
        int gr = r0 - 1 + row; if (gr < 0) gr = 0;
        float4 v = *(const float4*)(Qg + (size_t)gr * HDIM + c4);
        stash_perm(sQ + row * 64, c4,
                   make_float4(f2tf(v.x), f2tf(v.y), f2tf(v.z), f2tf(v.w)),
                   swz(row));
    }
    __syncthreads();

    // ---- persistent A-fragments: aQ (rows +1 / +9), aQp (rows +0 / +8) ----
    uint32_t aQ[8][4], aQp[8][4];
#pragma unroll
    for (int kb = 0; kb < 4; kb++) {
        float4 f;
        f = frag4(sQ, 64, 1 + rA, kb, t);
        aQ[2*kb][0] = U(f.x); aQ[2*kb][2] = U(f.y);
        aQ[2*kb+1][0] = U(f.z); aQ[2*kb+1][2] = U(f.w);
        f = frag4(sQ, 64, 9 + rA, kb, t);
        aQ[2*kb][1] = U(f.x); aQ[2*kb][3] = U(f.y);
        aQ[2*kb+1][1] = U(f.z); aQ[2*kb+1][3] = U(f.w);
        f = frag4(sQ, 64, rA, kb, t);
        aQp[2*kb][0] = U(f.x); aQp[2*kb][2] = U(f.y);
        aQp[2*kb+1][0] = U(f.z); aQp[2*kb+1][2] = U(f.w);
        f = frag4(sQ, 64, 8 + rA, kb, t);
        aQp[2*kb][1] = U(f.x); aQp[2*kb][3] = U(f.y);
        aQp[2*kb+1][1] = U(f.z); aQp[2*kb+1][3] = U(f.w);
    }

    float Oacc[8][4];
#pragma unroll
    for (int i = 0; i < 8; i++)
#pragma unroll
        for (int e = 0; e < 4; e++) Oacc[i][e] = 0.f;
    float m0r = -1e30f, m1r = -1e30f;
    float l0r = 0.f,    l1r = 0.f;

    for (int j = 0; j <= qt; j++) {
        const int c0 = j * 64;
        const int ph = (j & 1) << 6;
        __syncthreads();   // previous iteration's smem readers done (incl. P in sQ)

        // ---- stage K (perm, raw fp32) and V (linear, cvt) ----
        for (int idx = tid; idx < 64 * 16; idx += 128) {
            int row = idx >> 4, c4 = (idx & 15) << 2;
            float4 kv = *(const float4*)(Kg + (size_t)(c0 + row) * HDIM + c4);
            stash_perm(sK + row * 64, c4, kv, swz(row));
            float4 vv = *(const float4*)(Vg + (size_t)(c0 + row) * HDIM + c4);
            float* dv = sV + row * WVp + c4;
            dv[0] = f2tf(vv.x); dv[1] = f2tf(vv.y); dv[2] = f2tf(vv.z); dv[3] = f2tf(vv.w);
        }
        // ---- stage E ring (perm, raw fp32): j==0 all 128 rows, else top 64 only ----
        const int elog0 = SEQ - r0 + c0 - 63;   // >= 1 always
        const int rbase = (j == 0) ? 0 : 64;
        for (int idx = tid; idx < (128 - rbase) * 16; idx += 128) {
            int row = rbase + (idx >> 4), c4 = (idx & 15) << 2;
            int el = elog0 + row;
            float4 ev = make_float4(0.f, 0.f, 0.f, 0.f);
            if (el < SEQ)
                ev = *(const float4*)(rel + (size_t)(el + (MAXLEN - SEQ)) * DIM + hcol + c4);
            int pr = row ^ ph;
            stash_perm(sE + pr * 64, c4, ev, swz(pr));
        }
        __syncthreads();

        // ---- G band = Qprev @ Ewin^T (warp-trimmed n-tiles) ----
        const int nt0 = 6 - 2 * w;
#pragma unroll
        for (int ntl = 0; ntl < 10; ntl++) {
            const int nt = nt0 + ntl;
            float ga[4] = {0.f, 0.f, 0.f, 0.f};
            const int pr = (nt * 8 + g) ^ ph;
            float4 f0 = frag4(sE, 64, pr, 0, t);
            float4 f1 = frag4(sE, 64, pr, 1, t);
            float4 f2 = frag4(sE, 64, pr, 2, t);
            float4 f3 = frag4(sE, 64, pr, 3, t);
            mma8(ga, aQp[0][0], aQp[0][1], aQp[0][2], aQp[0][3], U(f0.x), U(f0.y));
            mma8(ga, aQp[1][0], aQp[1][1], aQp[1][2], aQp[1][3], U(f0.z), U(f0.w));
            mma8(ga, aQp[2][0], aQp[2][1], aQp[2][2], aQp[2][3], U(f1.x), U(f1.y));
            mma8(ga, aQp[3][0], aQp[3][1], aQp[3][2], aQp[3][3], U(f1.z), U(f1.w));
            mma8(ga, aQp[4][0], aQp[4][1], aQp[4][2], aQp[4][3], U(f2.x), U(f2.y));
            mma8(ga, aQp[5][0], aQp[5][1], aQp[5][2], aQp[5][3], U(f2.z), U(f2.w));
            mma8(ga, aQp[6][0], aQp[6][1], aQp[6][2], aQp[6][3], U(f3.x), U(f3.y));
            mma8(ga, aQp[7][0], aQp[7][1], aQp[7][2], aQp[7][3], U(f3.z), U(f3.w));
            const int cc = nt * 8 + 2 * t;
            const int i0 = cc + rA - 63;
            const int i2 = i0 + 8;
            if (i0 >= 0     && i0 < 64)     sGb[(rA)     * GBW + i0]     = ga[0];
            if (i0 + 1 >= 0 && i0 + 1 < 64) sGb[(rA)     * GBW + i0 + 1] = ga[1];
            if (i2 >= 0     && i2 < 64)     sGb[(rA + 8) * GBW + i2]     = ga[2];
            if (i2 + 1 >= 0 && i2 + 1 < 64) sGb[(rA + 8) * GBW + i2 + 1] = ga[3];
        }
        __syncwarp();

        // ---- S = Q @ K^T + srel (band gather), mask, scale ----
        float Sreg[8][4];
        float tmax0 = -1e30f, tmax1 = -1e30f;
#pragma unroll
        for (int nt = 0; nt < 8; nt++) {
            float* s = Sreg[nt];
            s[0] = s[1] = s[2] = s[3] = 0.f;
            const int kr = nt * 8 + g;
            float4 f0 = frag4(sK, 64, kr, 0, t);
            float4 f1 = frag4(sK, 64, kr, 1, t);
            float4 f2 = frag4(sK, 64, kr, 2, t);
            float4 f3 = frag4(sK, 64, kr, 3, t);
            mma8(s, aQ[0][0], aQ[0][1], aQ[0][2], aQ[0][3], U(f0.x), U(f0.y));
            mma8(s, aQ[1][0], aQ[1][1], aQ[1][2], aQ[1][3], U(f0.z), U(f0.w));
            mma8(s, aQ[2][0], aQ[2][1], aQ[2][2], aQ[2][3], U(f1.x), U(f1.y));
            mma8(s, aQ[3][0], aQ[3][1], aQ[3][2], aQ[3][3], U(f1.z), U(f1.w));
            mma8(s, aQ[4][0], aQ[4][1], aQ[4][2], aQ[4][3], U(f2.x), U(f2.y));
            mma8(s, aQ[5][0], aQ[5][1], aQ[5][2], aQ[5][3], U(f2.z), U(f2.w));
            mma8(s, aQ[6][0], aQ[6][1], aQ[6][2], aQ[6][3], U(f3.x), U(f3.y));
            mma8(s, aQ[7][0], aQ[7][1], aQ[7][2], aQ[7][3], U(f3.z), U(f3.w));

            const int cc0 = nt * 8 + 2 * t;
            float v;
            v = (s[0] + sGb[rA * GBW + cc0]) * 0.125f;
            if (c0 + cc0 > r0 + rA) v = -1e30f;
            s[0] = v; tmax0 = fmaxf(tmax0, v);

            v = (s[1] + sGb[rA * GBW + cc0 + 1]) * 0.125f;
            if (c0 + cc0 + 1 > r0 + rA) v = -1e30f;
            s[1] = v; tmax0 = fmaxf(tmax0, v);

            v = (s[2] + sGb[(rA + 8) * GBW + cc0]) * 0.125f;
            if (c0 + cc0 > r0 + rA + 8) v = -1e30f;
            s[2] = v; tmax1 = fmaxf(tmax1, v);

            v = (s[3] + sGb[(rA + 8) * GBW + cc0 + 1]) * 0.125f;
            if (c0 + cc0 + 1 > r0 + rA + 8) v = -1e30f;
            s[3] = v; tmax1 = fmaxf(tmax1, v);
        }

        // quad reductions (lanes sharing rows)
        tmax0 = fmaxf(tmax0, __shfl_xor_sync(0xffffffffu, tmax0, 1));
        tmax0 = fmaxf(tmax0, __shfl_xor_sync(0xffffffffu, tmax0, 2));
        tmax1 = fmaxf(tmax1, __shfl_xor_sync(0xffffffffu, tmax1, 1));
        tmax1 = fmaxf(tmax1, __shfl_xor_sync(0xffffffffu, tmax1, 2));

        float mn0 = fmaxf(m0r, tmax0), mn1 = fmaxf(m1r, tmax1);
        float f0s = __expf(m0r - mn0), f1s = __expf(m1r - mn1);
        float rs0 = 0.f, rs1 = 0.f;
#pragma unroll
        for (int nt = 0; nt < 8; nt++) {
            float* s = Sreg[nt];
            s[0] = __expf(s[0] - mn0); s[1] = __expf(s[1] - mn0);
            s[2] = __expf(s[2] - mn1); s[3] = __expf(s[3] - mn1);
            rs0 += s[0] + s[1];
            rs1 += s[2] + s[3];
        }
        rs0 += __shfl_xor_sync(0xffffffffu, rs0, 1);
        rs0 += __shfl_xor_sync(0xffffffffu, rs0, 2);
        rs1 += __shfl_xor_sync(0xffffffffu, rs1, 1);
        rs1 += __shfl_xor_sync(0xffffffffu, rs1, 2);

        m0r = mn0; m1r = mn1;
        l0r = l0r * f0s + rs0;
        l1r = l1r * f1s + rs1;
#pragma unroll
        for (int dn = 0; dn < 8; dn++) {
            Oacc[dn][0] *= f0s; Oacc[dn][1] *= f0s;
            Oacc[dn][2] *= f1s; Oacc[dn][3] *= f1s;
        }

        // ---- store P permuted into sP (= dead sQ region), then aP via LDS.128 ----
        __syncwarp();
#pragma unroll
        for (int nt = 0; nt < 8; nt++) {
            int c = nt * 8 + 2 * t;
            int ch = 4 * (c >> 4) + (c & 3);      // c+1 has (c&3)+1 (c even)
            int wd = (c & 15) >> 2;
            int s0 = swz(rA), s1 = swz(rA + 8);
            sP[(rA)     * 64 + 4 * ((ch)     ^ s0) + wd] = f2tf(Sreg[nt][0]);
            sP[(rA)     * 64 + 4 * ((ch + 1) ^ s0) + wd] = f2tf(Sreg[nt][1]);
            sP[(rA + 8) * 64 + 4 * ((ch)     ^ s1) + wd] = f2tf(Sreg[nt][2]);
            sP[(rA + 8) * 64 + 4 * ((ch + 1) ^ s1) + wd] = f2tf(Sreg[nt][3]);
        }
        __syncwarp();

        uint32_t aP[8][4];
#pragma unroll
        for (int kb = 0; kb < 4; kb++) {
            float4 f;
            f = frag4(sP, 64, rA, kb, t);
            aP[2*kb][0] = U(f.x); aP[2*kb][2] = U(f.y);
            aP[2*kb+1][0] = U(f.z); aP[2*kb+1][2] = U(f.w);
            f = frag4(sP, 64, rA + 8, kb, t);
            aP[2*kb][1] = U(f.x); aP[2*kb][3] = U(f.y);
            aP[2*kb+1][1] = U(f.z); aP[2*kb+1][3] = U(f.w);
        }

        // ---- O += P @ V (V scalar reads, transposed access) ----
#pragma unroll
        for (int dn = 0; dn < 8; dn++) {
            const int nb = dn * 8 + g;
#pragma unroll
            for (int ks = 0; ks < 8; ks++) {
                int kk = ks * 8;
                uint32_t b0 = U(sV[(kk + t)     * WVp + nb]);
                uint32_t b1 = U(sV[(kk + t + 4) * WVp + nb]);
                mma8(Oacc[dn], aP[ks][0], aP[ks][1], aP[ks][2], aP[ks][3], b0, b1);
            }
        }
    }

    // ---- normalize and write O in [b][n][h*HD+hd] layout ----
    float inv0 = 1.f / l0r, inv1 = 1.f / l1r;
    float* Og = g_O + (size_t)b * SEQ * DIM + (size_t)r0 * DIM + hcol;
#pragma unroll
    for (int dn = 0; dn < 8; dn++) {
        int d0 = dn * 8 + 2 * t;
        Og[(size_t)(rA)     * DIM + d0]     = Oacc[dn][0] * inv0;
        Og[(size_t)(rA)     * DIM + d0 + 1] = Oacc[dn][1] * inv0;
        Og[(size_t)(rA + 8) * DIM + d0]     = Oacc[dn][2] * inv1;
        Og[(size_t)(rA + 8) * DIM + d0 + 1] = Oacc[dn][3] * inv1;
    }
}

// ---------------- launch ----------------
extern "C" void kernel_launch(void* const* d_in, const int* in_sizes, int n_in,
                              void* d_out, int out_size)
{
    const float* x   = (const float*)d_in[0];
    const float* Wq  = (const float*)d_in[1];
    const float* Wk  = (const float*)d_in[2];
    const float* Wv  = (const float*)d_in[3];
    const float* Wp  = (const float*)d_in[4];
    const float* bp  = (const float*)d_in[5];
    const float* rel = (const float*)d_in[6];
    float* out = (float*)d_out;

    cudaFuncSetAttribute(attn_kernel,
                         cudaFuncAttributeMaxDynamicSharedMemorySize,
                         ATTN_SMEM_BYTES);

    gemm_tn<1><<<dim3(DIM / 128, BN / 128, 3), 256>>>(x, Wq, Wk, Wv, nullptr, nullptr);
    attn_kernel<<<dim3(SEQ / 64, BATCH * NHEAD), 128, ATTN_SMEM_BYTES>>>(rel);
    gemm_tn<0><<<dim3(DIM / 128, BN / 128), 256>>>(nullptr, Wp, nullptr, nullptr, bp, out);
}